// round 10
// baseline (speedup 1.0000x reference)
#include <cuda_runtime.h>
#include <cuda_bf16.h>
#include <cstdint>
#include <math.h>

#define Bc 64
#define Tc 512
#define Ic 512
#define Hc 512
#define Oc 512

// Scratch
__device__ uint32_t g_z16 [(long)Bc * Tc * Hc / 2];  // z (bf16x2)
__device__ uint32_t g_x16 [(long)Bc * Tc * Ic / 2];  // x as bf16x2
__device__ uint32_t g_zr16[(long)Bc * Tc * Hc / 2];  // zr (bf16x2)
__device__ uint32_t g_hn16[(long)Bc * Tc * Hc / 2];  // h_new (bf16x2)
__device__ float    g_hpr[Bc * Hc];
__device__ float    g_hpz[Bc * Hc];
__device__ __nv_bfloat16 g_WT16[5l * 512 * 512];     // W^T bf16 [sel][n][k]
// slabs: 0=Wr_x 1=Wz_x 2=Wh_x 3=Wh_h 4=Wo

__device__ __forceinline__ float sigmoidf_(float x) { return 1.0f / (1.0f + expf(-x)); }

__device__ __forceinline__ uint32_t pk(float lo, float hi) {
    __nv_bfloat162 h = __floats2bfloat162_rn(lo, hi);
    return *reinterpret_cast<uint32_t*>(&h);
}
__device__ __forceinline__ float2 upk(uint32_t u) {
    __nv_bfloat162 h = *reinterpret_cast<__nv_bfloat162*>(&u);
    return __bfloat1622float2(h);
}

__device__ __forceinline__ uint32_t smem_u32(const void* p) {
    uint32_t a;
    asm("{ .reg .u64 t; cvta.to.shared.u64 t, %1; cvt.u32.u64 %0, t; }" : "=r"(a) : "l"(p));
    return a;
}

__device__ __forceinline__ void mma_bf16(float* c, const uint32_t* a, const uint32_t* b) {
    asm volatile(
        "mma.sync.aligned.m16n8k16.row.col.f32.bf16.bf16.f32 "
        "{%0,%1,%2,%3}, {%4,%5,%6,%7}, {%8,%9}, {%0,%1,%2,%3};"
        : "+f"(c[0]), "+f"(c[1]), "+f"(c[2]), "+f"(c[3])
        : "r"(a[0]), "r"(a[1]), "r"(a[2]), "r"(a[3]), "r"(b[0]), "r"(b[1]));
}

__device__ __forceinline__ void ldm4(uint32_t* r, uint32_t addr) {
    asm volatile("ldmatrix.sync.aligned.m8n8.x4.shared.b16 {%0,%1,%2,%3}, [%4];"
                 : "=r"(r[0]), "=r"(r[1]), "=r"(r[2]), "=r"(r[3]) : "r"(addr));
}

#define CP16(saddr, gptr) asm volatile("cp.async.cg.shared.global [%0], [%1], 16;" :: "r"(saddr), "l"(gptr))
#define CP_COMMIT()       asm volatile("cp.async.commit_group;" ::: "memory")
#define CP_WAIT1()        asm volatile("cp.async.wait_group 1;" ::: "memory")
#define CP_WAIT0()        asm volatile("cp.async.wait_group 0;" ::: "memory")

#define PITCH 36
#define ROWPB (PITCH * 4)                 // 144 bytes per row
#define STGB  (384 * ROWPB)               // bytes per stage (55296): 256 A rows + 128 B rows
#define WSLAB 524288                      // bytes per weight slab in g_WT16

// ---------------------------------------------------------------------------
// bf16 mma.sync GEMM. CTA = 256 M-rows x 128 B-rows, 256 thr, 8 warps
// (4M x 2N), warp tile 64x64 (MODE 0: 64x32 per weight x 2 weights).
// BK=64, cp.async 3-stage, ldmatrix x4 frags, pitch 36 u32.
// Per k-step: 8 LDSM -> 32 MMA (128B SMEM per MMA).
//
// MODE 0: W=2 (Wr_x, Wz_x), A = x16 ((b,t) map), N-tile 64.
//         Epi: r,z -> zr(bf16), z(bf16).
// MODE 1: K=1024: A = [zr | x], B = [Wh_h ; Wh_x], N-tile 128.
//         Epi: hn = (1-z)h0 + z*tanh(acc+bh) -> bf16.
// MODE 2: K=512: A = hn, B = Wo, N-tile 128. Epi: sigmoid -> out.
// ---------------------------------------------------------------------------
template <int MODE>
__global__ __launch_bounds__(256, 1)
void kgemm(float* __restrict__ Cout, const float* __restrict__ bias,
           const float* __restrict__ h0, int Nt, int Tfull)
{
    constexpr int CHUNKS = (MODE == 1) ? 16 : 8;
    constexpr int W      = (MODE == 0) ? 2 : 1;
    constexpr int NT     = (MODE == 0) ? 4 : 8;
    constexpr int NTILE  = (MODE == 0) ? 64 : 128;
    constexpr int WNW    = (MODE == 0) ? 32 : 64;
    constexpr int NCHT   = 12;           // 16B chunks per thread (8 A + 4 B)

    extern __shared__ uint32_t sm[];
    const uint32_t sbase = smem_u32(sm);

    const int tid = threadIdx.x;
    const int wid = tid >> 5, lid = tid & 31;
    const int g = lid >> 2, t = lid & 3;
    const int warpM = wid & 3;           // 64-row slabs
    const int warpN = wid >> 2;          // 0..1
    const int m0 = blockIdx.y * 256;
    const int n0 = blockIdx.x * NTILE;

    const char* xb  = (const char*)g_x16;
    const char* zrb = (const char*)g_zr16;
    const char* hnb = (const char*)g_hn16;
    const char* wtb = (const char*)g_WT16;

    // ---- per-slot byte offsets: slots 0..7 = A rows, 8..11 = B rows ----
    uint32_t offP[NCHT];
    uint32_t offX[8];
    uint32_t sofb[NCHT];
#pragma unroll
    for (int i = 0; i < NCHT; i++) {
        if (i < 8) {
            int c = tid + 256 * i;
            int row = c >> 3, q = c & 7;
            int gm = m0 + row;
            uint32_t xoff = (uint32_t)((long)(gm / Nt) * Tfull + (gm % Nt)) * 1024u + q * 16;
            if (MODE == 0) offP[i] = xoff;
            else           offP[i] = (uint32_t)gm * 1024u + q * 16;
            if (MODE == 1) offX[i] = xoff;
            sofb[i] = (uint32_t)row * ROWPB + q * 16;
        } else {
            int c2 = tid + 256 * (i - 8);
            int brow = c2 >> 3, q = c2 & 7;
            if (MODE == 0) {
                int sel = brow >> 6, nr = brow & 63;     // 0=Wr_x, 1=Wz_x
                offP[i] = (uint32_t)sel * WSLAB + (uint32_t)(n0 + nr) * 1024u + q * 16;
            } else {
                offP[i] = (uint32_t)(n0 + brow) * 1024u + q * 16;   // slab added per chunk
            }
            sofb[i] = (uint32_t)(256 + brow) * ROWPB + q * 16;
        }
    }

    // ---- ldmatrix per-lane base addresses ----
    const uint32_t a_addr = sbase + (uint32_t)(warpM * 64 + (lid & 15)) * ROWPB
                          + ((lid & 16) ? 16 : 0);
    const int b_row = ((lid & 16) ? 8 : 0) + (lid & 7);
    const uint32_t b_addr = sbase + (uint32_t)(256 + b_row) * ROWPB + ((lid & 8) ? 16 : 0);

    uint32_t bgrp_off[4];   // B group base rows * 144
#pragma unroll
    for (int gb = 0; gb < 4; gb++) {
        int base = (MODE == 0) ? ((gb >> 1) * 64 + warpN * 32 + (gb & 1) * 16)   // (w, sub)
                               : (warpN * 64 + gb * 16);
        bgrp_off[gb] = (uint32_t)base * ROWPB;
    }

    float c[W][4][NT][4];
#pragma unroll
    for (int w = 0; w < W; w++)
#pragma unroll
        for (int mt = 0; mt < 4; mt++)
#pragma unroll
            for (int nt = 0; nt < NT; nt++)
#pragma unroll
                for (int q = 0; q < 4; q++) c[w][mt][nt][q] = 0.0f;

    // ---- cp.async issue for (slot i, chunk kt) ----
    auto issue = [&](int i, int kt, uint32_t stb) {
        const char* src;
        if (MODE == 0) {
            src = ((i < 8) ? xb : wtb) + offP[i] + kt * 128;
        } else if (MODE == 1) {
            if (i < 8) src = (kt < 8) ? (zrb + offP[i] + kt * 128)
                                      : (xb + offX[i] + (kt - 8) * 128);
            else       src = wtb + offP[i] + ((kt < 8) ? 3u : 2u) * WSLAB + (kt & 7) * 128;
        } else {
            src = ((i < 8) ? (hnb + offP[i]) : (wtb + offP[i] + 4u * WSLAB)) + kt * 128;
        }
        CP16(sbase + stb + sofb[i], src);
    };

    // ---- prologue: chunks 0,1 ----
#pragma unroll
    for (int i = 0; i < NCHT; i++) issue(i, 0, 0);
    CP_COMMIT();
#pragma unroll
    for (int i = 0; i < NCHT; i++) issue(i, 1, STGB);
    CP_COMMIT();
    CP_WAIT1();
    __syncthreads();

    // ---- mainloop ----
    for (int kt = 0; kt < CHUNKS; kt++) {
        const uint32_t stb = (uint32_t)(kt % 3) * STGB;
        const bool pf = (kt < CHUNKS - 2);
        const uint32_t nstb = (uint32_t)((kt + 2) % 3) * STGB;

#pragma unroll
        for (int ks = 0; ks < 4; ks++) {
            uint32_t af4[4][4];
#pragma unroll
            for (int mt = 0; mt < 4; mt++)
                ldm4(af4[mt], a_addr + stb + (uint32_t)mt * (16 * ROWPB) + ks * 32);
            uint32_t bf4[4][4];
#pragma unroll
            for (int gb = 0; gb < 4; gb++)
                ldm4(bf4[gb], b_addr + stb + bgrp_off[gb] + ks * 32);

            if (pf) {
                issue(3 * ks + 0, kt + 2, nstb);
                issue(3 * ks + 1, kt + 2, nstb);
                issue(3 * ks + 2, kt + 2, nstb);
            }

#pragma unroll
            for (int w = 0; w < W; w++)
#pragma unroll
                for (int mt = 0; mt < 4; mt++)
#pragma unroll
                    for (int nt = 0; nt < NT; nt++) {
                        const int gb = (MODE == 0) ? (w * 2 + (nt >> 1)) : (nt >> 1);
                        mma_bf16(c[w][mt][nt], af4[mt], &bf4[gb][(nt & 1) * 2]);
                    }
        }

        if (pf) CP_COMMIT();
        if (kt < CHUNKS - 1) {
            if (pf) CP_WAIT1(); else CP_WAIT0();
            __syncthreads();
        }
    }

    // ---- epilogue ----
#pragma unroll
    for (int mt = 0; mt < 4; mt++) {
#pragma unroll
        for (int rh = 0; rh < 2; rh++) {
            const int m = m0 + warpM * 64 + mt * 16 + g + rh * 8;
            const int b = m / Nt;
#pragma unroll
            for (int nt = 0; nt < NT; nt++) {
                const int n = n0 + warpN * WNW + nt * 8 + t * 2;
                const long hidx = (long)m * 256 + (n >> 1);
                if (MODE == 0) {
                    float vr0 = c[0][mt][nt][rh * 2 + 0], vr1 = c[0][mt][nt][rh * 2 + 1];
                    float vz0 = c[1 % W][mt][nt][rh * 2 + 0], vz1 = c[1 % W][mt][nt][rh * 2 + 1];
                    float r0 = sigmoidf_(vr0 + g_hpr[b * 512 + n]);
                    float r1 = sigmoidf_(vr1 + g_hpr[b * 512 + n + 1]);
                    float z0 = sigmoidf_(vz0 + g_hpz[b * 512 + n]);
                    float z1 = sigmoidf_(vz1 + g_hpz[b * 512 + n + 1]);
                    g_zr16[hidx] = pk(z0 * r0, z1 * r1);
                    g_z16[hidx]  = pk(z0, z1);
                } else if (MODE == 1) {
                    float v0 = c[0][mt][nt][rh * 2 + 0], v1 = c[0][mt][nt][rh * 2 + 1];
                    float2 zv = upk(g_z16[hidx]);
                    float2 hv = *(const float2*)(h0 + b * 512 + n);
                    float2 bv = *(const float2*)(bias + n);
                    float o0 = (1.0f - zv.x) * hv.x + zv.x * tanhf(v0 + bv.x);
                    float o1 = (1.0f - zv.y) * hv.y + zv.y * tanhf(v1 + bv.y);
                    g_hn16[hidx] = pk(o0, o1);
                } else {
                    float v0 = c[0][mt][nt][rh * 2 + 0], v1 = c[0][mt][nt][rh * 2 + 1];
                    float2 bv = *(const float2*)(bias + n);
                    *(float2*)(Cout + (long)m * 512 + n) =
                        make_float2(sigmoidf_(v0 + bv.x), sigmoidf_(v1 + bv.y));
                }
            }
        }
    }
}

// ---------------------------------------------------------------------------
__global__ void cvt_x_kernel(const float* __restrict__ src, uint32_t* __restrict__ dst) {
    long i = (long)blockIdx.x * blockDim.x + threadIdx.x;
    float4 v = ((const float4*)src)[i];
    ((uint2*)dst)[i] = make_uint2(pk(v.x, v.y), pk(v.z, v.w));
}

__global__ void transpose_all_bf16(const float* __restrict__ Wr, const float* __restrict__ Wz,
                                   const float* __restrict__ Wh, const float* __restrict__ Wo,
                                   __nv_bfloat16* __restrict__ dst) {
    __shared__ float tbuf[32][33];
    const int sel = blockIdx.z;
    const float* src = (sel == 0) ? Wr : (sel == 1) ? Wz : (sel == 2) ? Wh
                     : (sel == 3) ? (Wh + (long)Ic * Hc) : Wo;
    __nv_bfloat16* d = dst + (long)sel * 512 * 512;
    int bx = blockIdx.x * 32, by = blockIdx.y * 32;
#pragma unroll
    for (int i = 0; i < 4; i++)
        tbuf[threadIdx.y + i * 8][threadIdx.x] = src[(long)(by + threadIdx.y + i * 8) * 512 + bx + threadIdx.x];
    __syncthreads();
#pragma unroll
    for (int i = 0; i < 4; i++)
        d[(long)(bx + threadIdx.y + i * 8) * 512 + by + threadIdx.x] =
            __float2bfloat16(tbuf[threadIdx.x][threadIdx.y + i * 8]);
}

__global__ void hpart_kernel(const float* __restrict__ h0, const float* __restrict__ Wr_h,
                             const float* __restrict__ br, const float* __restrict__ Wz_h,
                             const float* __restrict__ bz) {
    int b = blockIdx.x, n = threadIdx.x;
    float ar = br[n], az = bz[n];
    const float* h0b = h0 + b * Hc;
    for (int k = 0; k < Hc; k++) {
        float h = h0b[k];
        ar = fmaf(h, Wr_h[k * Hc + n], ar);
        az = fmaf(h, Wz_h[k * Hc + n], az);
    }
    g_hpr[b * Hc + n] = ar;
    g_hpz[b * Hc + n] = az;
}

__global__ void copy_h0_kernel(const float* __restrict__ h0, float* __restrict__ dst) {
    int i = blockIdx.x * blockDim.x + threadIdx.x;
    dst[i] = h0[i];
}

// ---------------------------------------------------------------------------
extern "C" void kernel_launch(void* const* d_in, const int* in_sizes, int n_in,
                              void* d_out, int out_size) {
    const float* x  = (const float*)d_in[0];
    const float* h0 = (const float*)d_in[1];
    const float* Wr = (const float*)d_in[2];
    const float* br = (const float*)d_in[3];
    const float* Wz = (const float*)d_in[4];
    const float* bz = (const float*)d_in[5];
    const float* Wh = (const float*)d_in[6];
    const float* bh = (const float*)d_in[7];
    const float* Wo = (const float*)d_in[8];
    const float* bo = (const float*)d_in[9];
    float* out = (float*)d_out;

    long os = out_size;
    int Tfull = in_sizes[0] / (Bc * Ic);
    int Nt;
    bool with_h0;
    if (os > (long)Bc * Hc && ((os - (long)Bc * Hc) % ((long)Bc * Oc)) == 0) {
        Nt = (int)((os - (long)Bc * Hc) / ((long)Bc * Oc));
        with_h0 = true;
    } else {
        Nt = (int)(os / ((long)Bc * Oc));
        with_h0 = false;
    }
    int M = Bc * Nt;

    const int smemB = 3 * STGB;   // 165888
    cudaFuncSetAttribute(kgemm<0>, cudaFuncAttributeMaxDynamicSharedMemorySize, smemB);
    cudaFuncSetAttribute(kgemm<1>, cudaFuncAttributeMaxDynamicSharedMemorySize, smemB);
    cudaFuncSetAttribute(kgemm<2>, cudaFuncAttributeMaxDynamicSharedMemorySize, smemB);

    __nv_bfloat16* wt;
    cudaGetSymbolAddress((void**)&wt, g_WT16);
    uint32_t* x16;
    cudaGetSymbolAddress((void**)&x16, g_x16);

    transpose_all_bf16<<<dim3(16, 16, 5), dim3(32, 8)>>>(Wr, Wz, Wh, Wo, wt);

    long x4 = (long)in_sizes[0] / 4;
    cvt_x_kernel<<<(unsigned)(x4 / 256), 256>>>(x, x16);

    hpart_kernel<<<Bc, Hc>>>(h0, Wr + (long)Ic * Hc, br, Wz + (long)Ic * Hc, bz);

    // Stage 1: r,z gates (Wr_x, Wz_x fused)
    kgemm<0><<<dim3(8, M / 256), 256, smemB>>>(nullptr, nullptr, nullptr, Nt, Tfull);
    // Stage 2: hn via K=1024 GEMM [zr|x] @ [Wh_h ; Wh_x]
    kgemm<1><<<dim3(4, M / 256), 256, smemB>>>(nullptr, bh, h0, Nt, Tfull);
    // Stage 3: out
    kgemm<2><<<dim3(4, M / 256), 256, smemB>>>(out, bo, nullptr, Nt, Tfull);

    if (with_h0)
        copy_h0_kernel<<<(Bc * Hc) / 256, 256>>>(h0, out + (long)M * Oc);
}

// round 11
// speedup vs baseline: 1.1738x; 1.1738x over previous
#include <cuda_runtime.h>
#include <cuda_bf16.h>
#include <cstdint>
#include <math.h>

#define Bc 64
#define Tc 512
#define Ic 512
#define Hc 512
#define Oc 512

// Scratch
__device__ uint32_t g_z16 [(long)Bc * Tc * Hc / 2];  // z (bf16x2)
__device__ uint32_t g_x16 [(long)Bc * Tc * Ic / 2];  // x as bf16x2
__device__ uint32_t g_zr16[(long)Bc * Tc * Hc / 2];  // zr (bf16x2)
__device__ uint32_t g_hn16[(long)Bc * Tc * Hc / 2];  // h_new (bf16x2)
__device__ float    g_hpr[Bc * Hc];
__device__ float    g_hpz[Bc * Hc];
__device__ __nv_bfloat16 g_WT16[5l * 512 * 512];     // W^T bf16 [sel][n][k]
// slabs: 0=Wr_x 1=Wz_x 2=Wh_x 3=Wh_h 4=Wo

__device__ __forceinline__ float sigmoidf_(float x) { return 1.0f / (1.0f + expf(-x)); }

__device__ __forceinline__ uint32_t pk(float lo, float hi) {
    __nv_bfloat162 h = __floats2bfloat162_rn(lo, hi);
    return *reinterpret_cast<uint32_t*>(&h);
}
__device__ __forceinline__ float2 upk(uint32_t u) {
    __nv_bfloat162 h = *reinterpret_cast<__nv_bfloat162*>(&u);
    return __bfloat1622float2(h);
}

__device__ __forceinline__ uint32_t smem_u32(const void* p) {
    uint32_t a;
    asm("{ .reg .u64 t; cvta.to.shared.u64 t, %1; cvt.u32.u64 %0, t; }" : "=r"(a) : "l"(p));
    return a;
}

__device__ __forceinline__ void mma_bf16(float* c, const uint32_t* a, const uint32_t* b) {
    asm volatile(
        "mma.sync.aligned.m16n8k16.row.col.f32.bf16.bf16.f32 "
        "{%0,%1,%2,%3}, {%4,%5,%6,%7}, {%8,%9}, {%0,%1,%2,%3};"
        : "+f"(c[0]), "+f"(c[1]), "+f"(c[2]), "+f"(c[3])
        : "r"(a[0]), "r"(a[1]), "r"(a[2]), "r"(a[3]), "r"(b[0]), "r"(b[1]));
}

__device__ __forceinline__ void ldm4(uint32_t* r, uint32_t addr) {
    asm volatile("ldmatrix.sync.aligned.m8n8.x4.shared.b16 {%0,%1,%2,%3}, [%4];"
                 : "=r"(r[0]), "=r"(r[1]), "=r"(r[2]), "=r"(r[3]) : "r"(addr));
}

#define CP16(saddr, gptr) asm volatile("cp.async.cg.shared.global [%0], [%1], 16;" :: "r"(saddr), "l"(gptr))
#define CP_COMMIT()       asm volatile("cp.async.commit_group;" ::: "memory")
#define CP_WAIT1()        asm volatile("cp.async.wait_group 1;" ::: "memory")
#define CP_WAIT0()        asm volatile("cp.async.wait_group 0;" ::: "memory")

#define PITCH 36
#define ROWPB (PITCH * 4)                 // 144 bytes per row
#define STGB  (256 * ROWPB)               // bytes per stage (36864)
#define WSLAB 524288                      // bytes per weight slab in g_WT16

// ---------------------------------------------------------------------------
// bf16 mma.sync GEMM, CTA 128 M-rows x 128 B-rows, BK=64, cp.async 3-stage,
// ldmatrix x4 frags, pitch 36 u32.
//
// MODE 0: 512 thr, 16 warps (4M x 4N, warp 32x16 per weight), W=2 accums
//         (Wr_x, Wz_x), A = x16 ((b,t) map), N-tile 64. Simple R8-style
//         chunk body: issue-all at top, straight LDSM+MMA.
//         Epi: r,z -> zr(bf16), z(bf16).
// MODE 1: 256 thr, 8 warps (4M x 2N), K=1024: A = [zr | x],
//         B = [Wh_h ; Wh_x], N-tile 128. Epi: hn -> bf16.
// MODE 2: 256 thr, 8 warps, K=512: A = hn, B = Wo. Epi: sigmoid -> out.
// ---------------------------------------------------------------------------
template <int MODE>
__global__ __launch_bounds__((MODE == 0) ? 512 : 256, (MODE == 0) ? 1 : 2)
void kgemm(float* __restrict__ Cout, const float* __restrict__ bias,
           const float* __restrict__ h0, int Nt, int Tfull)
{
    constexpr int THR    = (MODE == 0) ? 512 : 256;
    constexpr int CHUNKS = (MODE == 1) ? 16 : 8;
    constexpr int W      = (MODE == 0) ? 2 : 1;
    constexpr int NT     = (MODE == 0) ? 2 : 8;
    constexpr int NGRP   = (MODE == 0) ? 2 : 4;
    constexpr int NTILE  = (MODE == 0) ? 64 : 128;
    constexpr int WNW    = (MODE == 0) ? 16 : 64;
    constexpr int NCHT   = 2048 / THR;            // 4 (M0) or 8 (M1/2)
    constexpr int AH     = NCHT / 2;              // slots < AH are A-rows

    extern __shared__ uint32_t sm[];
    const uint32_t sbase = smem_u32(sm);

    const int tid = threadIdx.x;
    const int wid = tid >> 5, lid = tid & 31;
    const int g = lid >> 2, t = lid & 3;
    const int warpM = wid & 3;
    const int warpN = wid >> 2;
    const int m0 = blockIdx.y * 128;
    const int n0 = blockIdx.x * NTILE;

    const char* xb  = (const char*)g_x16;
    const char* zrb = (const char*)g_zr16;
    const char* hnb = (const char*)g_hn16;
    const char* wtb = (const char*)g_WT16;

    // ---- per-slot byte offsets ----
    uint32_t offP[NCHT];
    uint32_t offX[AH];
    uint32_t sofb[NCHT];
#pragma unroll
    for (int i = 0; i < NCHT; i++) {
        int c = tid + THR * i;
        if (i < AH) {
            int row = c >> 3, q = c & 7;
            int gm = m0 + row;
            uint32_t xoff = (uint32_t)((long)(gm / Nt) * Tfull + (gm % Nt)) * 1024u + q * 16;
            if (MODE == 0) offP[i] = xoff;
            else           offP[i] = (uint32_t)gm * 1024u + q * 16;
            if (MODE == 1) offX[i] = xoff;
            sofb[i] = (uint32_t)row * ROWPB + q * 16;
        } else {
            int c2 = c - 1024;
            int brow = c2 >> 3, q = c2 & 7;
            if (MODE == 0) {
                int sel = brow >> 6, nr = brow & 63;     // 0=Wr_x, 1=Wz_x
                offP[i] = (uint32_t)sel * WSLAB + (uint32_t)(n0 + nr) * 1024u + q * 16;
            } else {
                offP[i] = (uint32_t)(n0 + brow) * 1024u + q * 16;   // slab added per chunk
            }
            sofb[i] = (uint32_t)(128 + brow) * ROWPB + q * 16;
        }
    }

    // ---- ldmatrix per-lane base addresses ----
    const uint32_t a_addr = sbase + (uint32_t)(warpM * 32 + (lid & 15)) * ROWPB
                          + ((lid & 16) ? 16 : 0);
    const int b_row = ((lid & 16) ? 8 : 0) + (lid & 7);
    const uint32_t b_addr = sbase + (uint32_t)(128 + b_row) * ROWPB + ((lid & 8) ? 16 : 0);

    uint32_t bgrp_off[NGRP];
#pragma unroll
    for (int gb = 0; gb < NGRP; gb++) {
        int base = (MODE == 0) ? (gb * 64 + warpN * 16) : (warpN * 64 + gb * 16);
        bgrp_off[gb] = (uint32_t)base * ROWPB;
    }

    float c[W][2][NT][4];
#pragma unroll
    for (int w = 0; w < W; w++)
#pragma unroll
        for (int mt = 0; mt < 2; mt++)
#pragma unroll
            for (int nt = 0; nt < NT; nt++)
#pragma unroll
                for (int q = 0; q < 4; q++) c[w][mt][nt][q] = 0.0f;

    // ---- cp.async issue for (slot i, chunk kt) ----
    auto issue = [&](int i, int kt, uint32_t stb) {
        const char* src;
        if (MODE == 0) {
            src = ((i < AH) ? xb : wtb) + offP[i] + kt * 128;
        } else if (MODE == 1) {
            if (i < AH) src = (kt < 8) ? (zrb + offP[i] + kt * 128)
                                       : (xb + offX[i < AH ? i : 0] + (kt - 8) * 128);
            else        src = wtb + offP[i] + ((kt < 8) ? 3u : 2u) * WSLAB + (kt & 7) * 128;
        } else {
            src = ((i < AH) ? (hnb + offP[i]) : (wtb + offP[i] + 4u * WSLAB)) + kt * 128;
        }
        CP16(sbase + stb + sofb[i], src);
    };

    // ---- prologue: chunks 0,1 -> stages 0,1 ----
#pragma unroll
    for (int i = 0; i < NCHT; i++) issue(i, 0, 0);
    CP_COMMIT();
#pragma unroll
    for (int i = 0; i < NCHT; i++) issue(i, 1, STGB);
    CP_COMMIT();
    CP_WAIT1();
    __syncthreads();

    // ---- mainloop ----
    for (int kt = 0; kt < CHUNKS; kt++) {
        const uint32_t stb = (uint32_t)(kt % 3) * STGB;
        const bool pf = (kt < CHUNKS - 2);
        const uint32_t nstb = (uint32_t)((kt + 2) % 3) * STGB;

        if (MODE == 0) {
            // R8-style: issue all DMA at chunk top, then straight LDSM+MMA
            if (pf) {
#pragma unroll
                for (int i = 0; i < NCHT; i++) issue(i, kt + 2, nstb);
            }
#pragma unroll
            for (int ks = 0; ks < 4; ks++) {
                uint32_t af4[2][4];
#pragma unroll
                for (int mt = 0; mt < 2; mt++)
                    ldm4(af4[mt], a_addr + stb + (uint32_t)mt * (16 * ROWPB) + ks * 32);
                uint32_t bf4[2][4];
#pragma unroll
                for (int gb = 0; gb < 2; gb++)
                    ldm4(bf4[gb], b_addr + stb + bgrp_off[gb] + ks * 32);
#pragma unroll
                for (int w = 0; w < 2; w++)
#pragma unroll
                    for (int mt = 0; mt < 2; mt++)
#pragma unroll
                        for (int nt = 0; nt < 2; nt++)
                            mma_bf16(c[w][mt][nt], af4[mt], &bf4[w][nt * 2]);
            }
        } else {
#pragma unroll
            for (int ks = 0; ks < 4; ks++) {
                if (pf) { issue(2 * ks, kt + 2, nstb); issue(2 * ks + 1, kt + 2, nstb); }
                uint32_t af4[2][4];
#pragma unroll
                for (int mt = 0; mt < 2; mt++)
                    ldm4(af4[mt], a_addr + stb + (uint32_t)mt * (16 * ROWPB) + ks * 32);
                uint32_t bf4[NGRP][4];
#pragma unroll
                for (int gb = 0; gb < NGRP; gb++)
                    ldm4(bf4[gb], b_addr + stb + bgrp_off[gb] + ks * 32);
#pragma unroll
                for (int mt = 0; mt < 2; mt++)
#pragma unroll
                    for (int nt = 0; nt < NT; nt++)
                        mma_bf16(c[0][mt][nt], af4[mt], &bf4[nt >> 1][(nt & 1) * 2]);
            }
        }

        if (pf) CP_COMMIT();
        if (kt < CHUNKS - 1) {
            if (pf) CP_WAIT1(); else CP_WAIT0();
            __syncthreads();
        }
    }

    // ---- epilogue ----
#pragma unroll
    for (int mt = 0; mt < 2; mt++) {
#pragma unroll
        for (int rh = 0; rh < 2; rh++) {
            const int m = m0 + warpM * 32 + mt * 16 + g + rh * 8;
            const int b = m / Nt;
#pragma unroll
            for (int nt = 0; nt < NT; nt++) {
                const int n = n0 + warpN * WNW + nt * 8 + t * 2;
                const long hidx = (long)m * 256 + (n >> 1);
                if (MODE == 0) {
                    float vr0 = c[0][mt][nt][rh * 2 + 0], vr1 = c[0][mt][nt][rh * 2 + 1];
                    float vz0 = c[1 % W][mt][nt][rh * 2 + 0], vz1 = c[1 % W][mt][nt][rh * 2 + 1];
                    float r0 = sigmoidf_(vr0 + g_hpr[b * 512 + n]);
                    float r1 = sigmoidf_(vr1 + g_hpr[b * 512 + n + 1]);
                    float z0 = sigmoidf_(vz0 + g_hpz[b * 512 + n]);
                    float z1 = sigmoidf_(vz1 + g_hpz[b * 512 + n + 1]);
                    g_zr16[hidx] = pk(z0 * r0, z1 * r1);
                    g_z16[hidx]  = pk(z0, z1);
                } else if (MODE == 1) {
                    float v0 = c[0][mt][nt][rh * 2 + 0], v1 = c[0][mt][nt][rh * 2 + 1];
                    float2 zv = upk(g_z16[hidx]);
                    float2 hv = *(const float2*)(h0 + b * 512 + n);
                    float2 bv = *(const float2*)(bias + n);
                    float o0 = (1.0f - zv.x) * hv.x + zv.x * tanhf(v0 + bv.x);
                    float o1 = (1.0f - zv.y) * hv.y + zv.y * tanhf(v1 + bv.y);
                    g_hn16[hidx] = pk(o0, o1);
                } else {
                    float v0 = c[0][mt][nt][rh * 2 + 0], v1 = c[0][mt][nt][rh * 2 + 1];
                    float2 bv = *(const float2*)(bias + n);
                    *(float2*)(Cout + (long)m * 512 + n) =
                        make_float2(sigmoidf_(v0 + bv.x), sigmoidf_(v1 + bv.y));
                }
            }
        }
    }
}

// ---------------------------------------------------------------------------
__global__ void cvt_x_kernel(const float* __restrict__ src, uint32_t* __restrict__ dst) {
    long i = (long)blockIdx.x * blockDim.x + threadIdx.x;
    float4 v = ((const float4*)src)[i];
    ((uint2*)dst)[i] = make_uint2(pk(v.x, v.y), pk(v.z, v.w));
}

__global__ void transpose_all_bf16(const float* __restrict__ Wr, const float* __restrict__ Wz,
                                   const float* __restrict__ Wh, const float* __restrict__ Wo,
                                   __nv_bfloat16* __restrict__ dst) {
    __shared__ float tbuf[32][33];
    const int sel = blockIdx.z;
    const float* src = (sel == 0) ? Wr : (sel == 1) ? Wz : (sel == 2) ? Wh
                     : (sel == 3) ? (Wh + (long)Ic * Hc) : Wo;
    __nv_bfloat16* d = dst + (long)sel * 512 * 512;
    int bx = blockIdx.x * 32, by = blockIdx.y * 32;
#pragma unroll
    for (int i = 0; i < 4; i++)
        tbuf[threadIdx.y + i * 8][threadIdx.x] = src[(long)(by + threadIdx.y + i * 8) * 512 + bx + threadIdx.x];
    __syncthreads();
#pragma unroll
    for (int i = 0; i < 4; i++)
        d[(long)(bx + threadIdx.y + i * 8) * 512 + by + threadIdx.x] =
            __float2bfloat16(tbuf[threadIdx.x][threadIdx.y + i * 8]);
}

__global__ void hpart_kernel(const float* __restrict__ h0, const float* __restrict__ Wr_h,
                             const float* __restrict__ br, const float* __restrict__ Wz_h,
                             const float* __restrict__ bz) {
    int b = blockIdx.x, n = threadIdx.x;
    float ar = br[n], az = bz[n];
    const float* h0b = h0 + b * Hc;
    for (int k = 0; k < Hc; k++) {
        float h = h0b[k];
        ar = fmaf(h, Wr_h[k * Hc + n], ar);
        az = fmaf(h, Wz_h[k * Hc + n], az);
    }
    g_hpr[b * Hc + n] = ar;
    g_hpz[b * Hc + n] = az;
}

__global__ void copy_h0_kernel(const float* __restrict__ h0, float* __restrict__ dst) {
    int i = blockIdx.x * blockDim.x + threadIdx.x;
    dst[i] = h0[i];
}

// ---------------------------------------------------------------------------
extern "C" void kernel_launch(void* const* d_in, const int* in_sizes, int n_in,
                              void* d_out, int out_size) {
    const float* x  = (const float*)d_in[0];
    const float* h0 = (const float*)d_in[1];
    const float* Wr = (const float*)d_in[2];
    const float* br = (const float*)d_in[3];
    const float* Wz = (const float*)d_in[4];
    const float* bz = (const float*)d_in[5];
    const float* Wh = (const float*)d_in[6];
    const float* bh = (const float*)d_in[7];
    const float* Wo = (const float*)d_in[8];
    const float* bo = (const float*)d_in[9];
    float* out = (float*)d_out;

    long os = out_size;
    int Tfull = in_sizes[0] / (Bc * Ic);
    int Nt;
    bool with_h0;
    if (os > (long)Bc * Hc && ((os - (long)Bc * Hc) % ((long)Bc * Oc)) == 0) {
        Nt = (int)((os - (long)Bc * Hc) / ((long)Bc * Oc));
        with_h0 = true;
    } else {
        Nt = (int)(os / ((long)Bc * Oc));
        with_h0 = false;
    }
    int M = Bc * Nt;

    const int smemB = 3 * STGB;   // 110592
    cudaFuncSetAttribute(kgemm<0>, cudaFuncAttributeMaxDynamicSharedMemorySize, smemB);
    cudaFuncSetAttribute(kgemm<1>, cudaFuncAttributeMaxDynamicSharedMemorySize, smemB);
    cudaFuncSetAttribute(kgemm<2>, cudaFuncAttributeMaxDynamicSharedMemorySize, smemB);

    __nv_bfloat16* wt;
    cudaGetSymbolAddress((void**)&wt, g_WT16);
    uint32_t* x16;
    cudaGetSymbolAddress((void**)&x16, g_x16);

    transpose_all_bf16<<<dim3(16, 16, 5), dim3(32, 8)>>>(Wr, Wz, Wh, Wo, wt);

    long x4 = (long)in_sizes[0] / 4;
    cvt_x_kernel<<<(unsigned)(x4 / 256), 256>>>(x, x16);

    hpart_kernel<<<Bc, Hc>>>(h0, Wr + (long)Ic * Hc, br, Wz + (long)Ic * Hc, bz);

    // Stage 1: r,z gates (Wr_x, Wz_x fused)
    kgemm<0><<<dim3(8, M / 128), 512, smemB>>>(nullptr, nullptr, nullptr, Nt, Tfull);
    // Stage 2: hn via K=1024 GEMM [zr|x] @ [Wh_h ; Wh_x]
    kgemm<1><<<dim3(4, M / 128), 256, smemB>>>(nullptr, bh, h0, Nt, Tfull);
    // Stage 3: out
    kgemm<2><<<dim3(4, M / 128), 256, smemB>>>(out, bo, nullptr, Nt, Tfull);

    if (with_h0)
        copy_h0_kernel<<<(Bc * Hc) / 256, 256>>>(h0, out + (long)M * Oc);
}

// round 12
// speedup vs baseline: 1.2529x; 1.0673x over previous
#include <cuda_runtime.h>
#include <cuda_bf16.h>
#include <cstdint>
#include <math.h>

#define Bc 64
#define Tc 512
#define Ic 512
#define Hc 512
#define Oc 512

// Scratch
__device__ uint32_t g_z16 [(long)Bc * Tc * Hc / 2];  // z (bf16x2)
__device__ uint32_t g_x16 [(long)Bc * Tc * Ic / 2];  // x as bf16x2
__device__ uint32_t g_zr16[(long)Bc * Tc * Hc / 2];  // zr (bf16x2)
__device__ uint32_t g_hn16[(long)Bc * Tc * Hc / 2];  // h_new (bf16x2)
__device__ float    g_hpr[Bc * Hc];
__device__ float    g_hpz[Bc * Hc];
__device__ __nv_bfloat16 g_WT16[5l * 512 * 512];     // W^T bf16 [sel][n][k]
// slabs: 0=Wr_x 1=Wz_x 2=Wh_x 3=Wh_h 4=Wo

__device__ __forceinline__ float sigmoidf_(float x) { return 1.0f / (1.0f + expf(-x)); }

__device__ __forceinline__ uint32_t pk(float lo, float hi) {
    __nv_bfloat162 h = __floats2bfloat162_rn(lo, hi);
    return *reinterpret_cast<uint32_t*>(&h);
}
__device__ __forceinline__ float2 upk(uint32_t u) {
    __nv_bfloat162 h = *reinterpret_cast<__nv_bfloat162*>(&u);
    return __bfloat1622float2(h);
}

__device__ __forceinline__ uint32_t smem_u32(const void* p) {
    uint32_t a;
    asm("{ .reg .u64 t; cvta.to.shared.u64 t, %1; cvt.u32.u64 %0, t; }" : "=r"(a) : "l"(p));
    return a;
}

__device__ __forceinline__ void mma_bf16(float* c, const uint32_t* a, const uint32_t* b) {
    asm volatile(
        "mma.sync.aligned.m16n8k16.row.col.f32.bf16.bf16.f32 "
        "{%0,%1,%2,%3}, {%4,%5,%6,%7}, {%8,%9}, {%0,%1,%2,%3};"
        : "+f"(c[0]), "+f"(c[1]), "+f"(c[2]), "+f"(c[3])
        : "r"(a[0]), "r"(a[1]), "r"(a[2]), "r"(a[3]), "r"(b[0]), "r"(b[1]));
}

__device__ __forceinline__ void ldm4(uint32_t* r, uint32_t addr) {
    asm volatile("ldmatrix.sync.aligned.m8n8.x4.shared.b16 {%0,%1,%2,%3}, [%4];"
                 : "=r"(r[0]), "=r"(r[1]), "=r"(r[2]), "=r"(r[3]) : "r"(addr));
}

#define CP16(saddr, gptr) asm volatile("cp.async.cg.shared.global [%0], [%1], 16;" :: "r"(saddr), "l"(gptr))
#define CP_COMMIT()       asm volatile("cp.async.commit_group;" ::: "memory")
#define CP_WAIT1()        asm volatile("cp.async.wait_group 1;" ::: "memory")
#define CP_WAIT0()        asm volatile("cp.async.wait_group 0;" ::: "memory")

#define PITCH 36
#define ROWPB (PITCH * 4)                 // 144 bytes per row
#define WSLAB 524288                      // bytes per weight slab in g_WT16

// ---------------------------------------------------------------------------
// bf16 mma.sync GEMM, CTA 128 M-rows, BK=64, cp.async 3-stage, ldmatrix x4,
// pitch 36 u32.
//
// MODE 0: 512 thr, 16 warps (4M x 4N), warp tile 32x32 PER WEIGHT (W=2:
//         Wr_x, Wz_x; 256 B rows), N-tile 128. Per k-step: 6 LDSM -> 16 MMA.
//         A = x16 ((b,t) map). Epi: r,z -> zr(bf16), z(bf16).
// MODE 1: 256 thr, 8 warps (4M x 2N), K=1024: A = [zr | x],
//         B = [Wh_h ; Wh_x], N-tile 128. Epi: hn -> bf16.
// MODE 2: 256 thr, 8 warps, K=512: A = hn, B = Wo. Epi: sigmoid -> out.
// ---------------------------------------------------------------------------
template <int MODE>
__global__ __launch_bounds__((MODE == 0) ? 512 : 256, (MODE == 0) ? 1 : 2)
void kgemm(float* __restrict__ Cout, const float* __restrict__ bias,
           const float* __restrict__ h0, int Nt, int Tfull)
{
    constexpr int THR    = (MODE == 0) ? 512 : 256;
    constexpr int CHUNKS = (MODE == 1) ? 16 : 8;
    constexpr int W      = (MODE == 0) ? 2 : 1;
    constexpr int NT     = (MODE == 0) ? 4 : 8;
    constexpr int WNW    = (MODE == 0) ? 32 : 64;
    constexpr int BROWS  = (MODE == 0) ? 256 : 128;
    constexpr int STGROWS = 128 + BROWS;
    constexpr uint32_t STGB = STGROWS * ROWPB;     // 55296 / 36864
    constexpr int NCHT   = STGROWS * 8 / THR;      // 6 (M0) / 8 (M1,2)
    constexpr int AH     = 1024 / THR;             // A slots: 2 / 4

    extern __shared__ uint32_t sm[];
    const uint32_t sbase = smem_u32(sm);

    const int tid = threadIdx.x;
    const int wid = tid >> 5, lid = tid & 31;
    const int g = lid >> 2, t = lid & 3;
    const int warpM = wid & 3;
    const int warpN = wid >> 2;
    const int m0 = blockIdx.y * 128;
    const int n0 = blockIdx.x * 128;

    const char* xb  = (const char*)g_x16;
    const char* zrb = (const char*)g_zr16;
    const char* hnb = (const char*)g_hn16;
    const char* wtb = (const char*)g_WT16;

    // ---- per-slot byte offsets: A chunks (c<1024), B chunks (rest) ----
    uint32_t offP[NCHT];
    uint32_t offX[AH];
    uint32_t sofb[NCHT];
#pragma unroll
    for (int i = 0; i < NCHT; i++) {
        int c = tid + THR * i;
        if (c < 1024) {
            int row = c >> 3, q = c & 7;
            int gm = m0 + row;
            uint32_t xoff = (uint32_t)((long)(gm / Nt) * Tfull + (gm % Nt)) * 1024u + q * 16;
            if (MODE == 0) offP[i] = xoff;
            else           offP[i] = (uint32_t)gm * 1024u + q * 16;
            if (MODE == 1) offX[i] = xoff;
            sofb[i] = (uint32_t)row * ROWPB + q * 16;
        } else {
            int c2 = c - 1024;
            int brow = c2 >> 3, q = c2 & 7;
            if (MODE == 0) {
                int sel = brow >> 7, nr = brow & 127;    // 0=Wr_x, 1=Wz_x
                offP[i] = (uint32_t)sel * WSLAB + (uint32_t)(n0 + nr) * 1024u + q * 16;
            } else {
                offP[i] = (uint32_t)(n0 + brow) * 1024u + q * 16;   // slab added per chunk
            }
            sofb[i] = (uint32_t)(128 + brow) * ROWPB + q * 16;
        }
    }

    // ---- ldmatrix per-lane base addresses ----
    const uint32_t a_addr = sbase + (uint32_t)(warpM * 32 + (lid & 15)) * ROWPB
                          + ((lid & 16) ? 16 : 0);
    const int b_row = ((lid & 16) ? 8 : 0) + (lid & 7);
    const uint32_t b_addr = sbase + (uint32_t)(128 + b_row) * ROWPB + ((lid & 8) ? 16 : 0);

    uint32_t bgrp_off[4];
#pragma unroll
    for (int gb = 0; gb < 4; gb++) {
        int base = (MODE == 0) ? ((gb >> 1) * 128 + warpN * 32 + (gb & 1) * 16)
                               : (warpN * 64 + gb * 16);
        bgrp_off[gb] = (uint32_t)base * ROWPB;
    }

    float c[W][2][NT][4];
#pragma unroll
    for (int w = 0; w < W; w++)
#pragma unroll
        for (int mt = 0; mt < 2; mt++)
#pragma unroll
            for (int nt = 0; nt < NT; nt++)
#pragma unroll
                for (int q = 0; q < 4; q++) c[w][mt][nt][q] = 0.0f;

    // ---- cp.async issue for (slot i, chunk kt) ----
    auto issue = [&](int i, int kt, uint32_t stb) {
        const char* src;
        if (MODE == 0) {
            src = ((i < AH) ? xb : wtb) + offP[i] + kt * 128;
        } else if (MODE == 1) {
            if (i < AH) src = (kt < 8) ? (zrb + offP[i] + kt * 128)
                                       : (xb + offX[i < AH ? i : 0] + (kt - 8) * 128);
            else        src = wtb + offP[i] + ((kt < 8) ? 3u : 2u) * WSLAB + (kt & 7) * 128;
        } else {
            src = ((i < AH) ? (hnb + offP[i]) : (wtb + offP[i] + 4u * WSLAB)) + kt * 128;
        }
        CP16(sbase + stb + sofb[i], src);
    };

    // ---- prologue: chunks 0,1 -> stages 0,1 ----
#pragma unroll
    for (int i = 0; i < NCHT; i++) issue(i, 0, 0);
    CP_COMMIT();
#pragma unroll
    for (int i = 0; i < NCHT; i++) issue(i, 1, STGB);
    CP_COMMIT();
    CP_WAIT1();
    __syncthreads();

    // ---- mainloop ----
    for (int kt = 0; kt < CHUNKS; kt++) {
        const uint32_t stb = (uint32_t)(kt % 3) * STGB;
        const bool pf = (kt < CHUNKS - 2);
        const uint32_t nstb = (uint32_t)((kt + 2) % 3) * STGB;

        if (MODE == 0) {
            if (pf) {
#pragma unroll
                for (int i = 0; i < NCHT; i++) issue(i, kt + 2, nstb);
            }
#pragma unroll
            for (int ks = 0; ks < 4; ks++) {
                uint32_t af4[2][4];
#pragma unroll
                for (int mt = 0; mt < 2; mt++)
                    ldm4(af4[mt], a_addr + stb + (uint32_t)mt * (16 * ROWPB) + ks * 32);
                uint32_t bf4[4][4];
#pragma unroll
                for (int gb = 0; gb < 4; gb++)
                    ldm4(bf4[gb], b_addr + stb + bgrp_off[gb] + ks * 32);
#pragma unroll
                for (int w = 0; w < 2; w++)
#pragma unroll
                    for (int mt = 0; mt < 2; mt++)
#pragma unroll
                        for (int nt = 0; nt < NT; nt++)
                            mma_bf16(c[w][mt][nt], af4[mt],
                                     &bf4[w * 2 + (nt >> 1)][(nt & 1) * 2]);
            }
        } else {
#pragma unroll
            for (int ks = 0; ks < 4; ks++) {
                if (pf) { issue(2 * ks, kt + 2, nstb); issue(2 * ks + 1, kt + 2, nstb); }
                uint32_t af4[2][4];
#pragma unroll
                for (int mt = 0; mt < 2; mt++)
                    ldm4(af4[mt], a_addr + stb + (uint32_t)mt * (16 * ROWPB) + ks * 32);
                uint32_t bf4[4][4];
#pragma unroll
                for (int gb = 0; gb < 4; gb++)
                    ldm4(bf4[gb], b_addr + stb + bgrp_off[gb] + ks * 32);
#pragma unroll
                for (int mt = 0; mt < 2; mt++)
#pragma unroll
                    for (int nt = 0; nt < NT; nt++)
                        mma_bf16(c[0][mt][nt], af4[mt], &bf4[nt >> 1][(nt & 1) * 2]);
            }
        }

        if (pf) CP_COMMIT();
        if (kt < CHUNKS - 1) {
            if (pf) CP_WAIT1(); else CP_WAIT0();
            __syncthreads();
        }
    }

    // ---- epilogue ----
#pragma unroll
    for (int mt = 0; mt < 2; mt++) {
#pragma unroll
        for (int rh = 0; rh < 2; rh++) {
            const int m = m0 + warpM * 32 + mt * 16 + g + rh * 8;
            const int b = m / Nt;
#pragma unroll
            for (int nt = 0; nt < NT; nt++) {
                const int n = n0 + warpN * WNW + nt * 8 + t * 2;
                const long hidx = (long)m * 256 + (n >> 1);
                if (MODE == 0) {
                    float vr0 = c[0][mt][nt][rh * 2 + 0], vr1 = c[0][mt][nt][rh * 2 + 1];
                    float vz0 = c[1 % W][mt][nt][rh * 2 + 0], vz1 = c[1 % W][mt][nt][rh * 2 + 1];
                    float r0 = sigmoidf_(vr0 + g_hpr[b * 512 + n]);
                    float r1 = sigmoidf_(vr1 + g_hpr[b * 512 + n + 1]);
                    float z0 = sigmoidf_(vz0 + g_hpz[b * 512 + n]);
                    float z1 = sigmoidf_(vz1 + g_hpz[b * 512 + n + 1]);
                    g_zr16[hidx] = pk(z0 * r0, z1 * r1);
                    g_z16[hidx]  = pk(z0, z1);
                } else if (MODE == 1) {
                    float v0 = c[0][mt][nt][rh * 2 + 0], v1 = c[0][mt][nt][rh * 2 + 1];
                    float2 zv = upk(g_z16[hidx]);
                    float2 hv = *(const float2*)(h0 + b * 512 + n);
                    float2 bv = *(const float2*)(bias + n);
                    float o0 = (1.0f - zv.x) * hv.x + zv.x * tanhf(v0 + bv.x);
                    float o1 = (1.0f - zv.y) * hv.y + zv.y * tanhf(v1 + bv.y);
                    g_hn16[hidx] = pk(o0, o1);
                } else {
                    float v0 = c[0][mt][nt][rh * 2 + 0], v1 = c[0][mt][nt][rh * 2 + 1];
                    float2 bv = *(const float2*)(bias + n);
                    *(float2*)(Cout + (long)m * 512 + n) =
                        make_float2(sigmoidf_(v0 + bv.x), sigmoidf_(v1 + bv.y));
                }
            }
        }
    }
}

// ---------------------------------------------------------------------------
__global__ void cvt_x_kernel(const float* __restrict__ src, uint32_t* __restrict__ dst) {
    long i = (long)blockIdx.x * blockDim.x + threadIdx.x;
    float4 v = ((const float4*)src)[i];
    ((uint2*)dst)[i] = make_uint2(pk(v.x, v.y), pk(v.z, v.w));
}

__global__ void transpose_all_bf16(const float* __restrict__ Wr, const float* __restrict__ Wz,
                                   const float* __restrict__ Wh, const float* __restrict__ Wo,
                                   __nv_bfloat16* __restrict__ dst) {
    __shared__ float tbuf[32][33];
    const int sel = blockIdx.z;
    const float* src = (sel == 0) ? Wr : (sel == 1) ? Wz : (sel == 2) ? Wh
                     : (sel == 3) ? (Wh + (long)Ic * Hc) : Wo;
    __nv_bfloat16* d = dst + (long)sel * 512 * 512;
    int bx = blockIdx.x * 32, by = blockIdx.y * 32;
#pragma unroll
    for (int i = 0; i < 4; i++)
        tbuf[threadIdx.y + i * 8][threadIdx.x] = src[(long)(by + threadIdx.y + i * 8) * 512 + bx + threadIdx.x];
    __syncthreads();
#pragma unroll
    for (int i = 0; i < 4; i++)
        d[(long)(bx + threadIdx.y + i * 8) * 512 + by + threadIdx.x] =
            __float2bfloat16(tbuf[threadIdx.x][threadIdx.y + i * 8]);
}

__global__ void hpart_kernel(const float* __restrict__ h0, const float* __restrict__ Wr_h,
                             const float* __restrict__ br, const float* __restrict__ Wz_h,
                             const float* __restrict__ bz) {
    int b = blockIdx.x, n = threadIdx.x;
    float ar = br[n], az = bz[n];
    const float* h0b = h0 + b * Hc;
    for (int k = 0; k < Hc; k++) {
        float h = h0b[k];
        ar = fmaf(h, Wr_h[k * Hc + n], ar);
        az = fmaf(h, Wz_h[k * Hc + n], az);
    }
    g_hpr[b * Hc + n] = ar;
    g_hpz[b * Hc + n] = az;
}

__global__ void copy_h0_kernel(const float* __restrict__ h0, float* __restrict__ dst) {
    int i = blockIdx.x * blockDim.x + threadIdx.x;
    dst[i] = h0[i];
}

// ---------------------------------------------------------------------------
extern "C" void kernel_launch(void* const* d_in, const int* in_sizes, int n_in,
                              void* d_out, int out_size) {
    const float* x  = (const float*)d_in[0];
    const float* h0 = (const float*)d_in[1];
    const float* Wr = (const float*)d_in[2];
    const float* br = (const float*)d_in[3];
    const float* Wz = (const float*)d_in[4];
    const float* bz = (const float*)d_in[5];
    const float* Wh = (const float*)d_in[6];
    const float* bh = (const float*)d_in[7];
    const float* Wo = (const float*)d_in[8];
    const float* bo = (const float*)d_in[9];
    float* out = (float*)d_out;

    long os = out_size;
    int Tfull = in_sizes[0] / (Bc * Ic);
    int Nt;
    bool with_h0;
    if (os > (long)Bc * Hc && ((os - (long)Bc * Hc) % ((long)Bc * Oc)) == 0) {
        Nt = (int)((os - (long)Bc * Hc) / ((long)Bc * Oc));
        with_h0 = true;
    } else {
        Nt = (int)(os / ((long)Bc * Oc));
        with_h0 = false;
    }
    int M = Bc * Nt;

    const int smem0  = 384 * ROWPB * 3;   // 165888
    const int smem12 = 256 * ROWPB * 3;   // 110592
    cudaFuncSetAttribute(kgemm<0>, cudaFuncAttributeMaxDynamicSharedMemorySize, smem0);
    cudaFuncSetAttribute(kgemm<1>, cudaFuncAttributeMaxDynamicSharedMemorySize, smem12);
    cudaFuncSetAttribute(kgemm<2>, cudaFuncAttributeMaxDynamicSharedMemorySize, smem12);

    __nv_bfloat16* wt;
    cudaGetSymbolAddress((void**)&wt, g_WT16);
    uint32_t* x16;
    cudaGetSymbolAddress((void**)&x16, g_x16);

    transpose_all_bf16<<<dim3(16, 16, 5), dim3(32, 8)>>>(Wr, Wz, Wh, Wo, wt);

    long x4 = (long)in_sizes[0] / 4;
    cvt_x_kernel<<<(unsigned)(x4 / 256), 256>>>(x, x16);

    hpart_kernel<<<Bc, Hc>>>(h0, Wr + (long)Ic * Hc, br, Wz + (long)Ic * Hc, bz);

    // Stage 1: r,z gates (Wr_x, Wz_x fused), N-tile 128
    kgemm<0><<<dim3(4, M / 128), 512, smem0>>>(nullptr, nullptr, nullptr, Nt, Tfull);
    // Stage 2: hn via K=1024 GEMM [zr|x] @ [Wh_h ; Wh_x]
    kgemm<1><<<dim3(4, M / 128), 256, smem12>>>(nullptr, bh, h0, Nt, Tfull);
    // Stage 3: out
    kgemm<2><<<dim3(4, M / 128), 256, smem12>>>(out, bo, nullptr, Nt, Tfull);

    if (with_h0)
        copy_h0_kernel<<<(Bc * Hc) / 256, 256>>>(h0, out + (long)M * Oc);
}

// round 13
// speedup vs baseline: 1.3024x; 1.0395x over previous
#include <cuda_runtime.h>
#include <cuda_bf16.h>
#include <cstdint>
#include <math.h>

#define Bc 64
#define Tc 512
#define Ic 512
#define Hc 512
#define Oc 512

// Scratch
__device__ uint32_t g_z16 [(long)Bc * Tc * Hc / 2];  // z (bf16x2)
__device__ uint32_t g_x16 [(long)Bc * Tc * Ic / 2];  // x as bf16x2
__device__ uint32_t g_zr16[(long)Bc * Tc * Hc / 2];  // zr (bf16x2)
__device__ uint32_t g_hn16[(long)Bc * Tc * Hc / 2];  // h_new (bf16x2)
__device__ float    g_hpr[Bc * Hc];
__device__ float    g_hpz[Bc * Hc];
__device__ __nv_bfloat16 g_WT16[5l * 512 * 512];     // W^T bf16 [sel][n][k]
// slabs: 0=Wr_x 1=Wz_x 2=Wh_x 3=Wh_h 4=Wo

__device__ __forceinline__ float sigmoidf_(float x) { return 1.0f / (1.0f + expf(-x)); }

__device__ __forceinline__ uint32_t pk(float lo, float hi) {
    __nv_bfloat162 h = __floats2bfloat162_rn(lo, hi);
    return *reinterpret_cast<uint32_t*>(&h);
}
__device__ __forceinline__ float2 upk(uint32_t u) {
    __nv_bfloat162 h = *reinterpret_cast<__nv_bfloat162*>(&u);
    return __bfloat1622float2(h);
}

__device__ __forceinline__ uint32_t smem_u32(const void* p) {
    uint32_t a;
    asm("{ .reg .u64 t; cvta.to.shared.u64 t, %1; cvt.u32.u64 %0, t; }" : "=r"(a) : "l"(p));
    return a;
}

__device__ __forceinline__ void mma_bf16(float* c, const uint32_t* a, const uint32_t* b) {
    asm volatile(
        "mma.sync.aligned.m16n8k16.row.col.f32.bf16.bf16.f32 "
        "{%0,%1,%2,%3}, {%4,%5,%6,%7}, {%8,%9}, {%0,%1,%2,%3};"
        : "+f"(c[0]), "+f"(c[1]), "+f"(c[2]), "+f"(c[3])
        : "r"(a[0]), "r"(a[1]), "r"(a[2]), "r"(a[3]), "r"(b[0]), "r"(b[1]));
}

__device__ __forceinline__ void ldm4(uint32_t* r, uint32_t addr) {
    asm volatile("ldmatrix.sync.aligned.m8n8.x4.shared.b16 {%0,%1,%2,%3}, [%4];"
                 : "=r"(r[0]), "=r"(r[1]), "=r"(r[2]), "=r"(r[3]) : "r"(addr));
}

#define CP16(saddr, gptr) asm volatile("cp.async.cg.shared.global [%0], [%1], 16;" :: "r"(saddr), "l"(gptr))
#define CP_COMMIT()       asm volatile("cp.async.commit_group;" ::: "memory")
#define CP_WAIT1()        asm volatile("cp.async.wait_group 1;" ::: "memory")
#define CP_WAIT0()        asm volatile("cp.async.wait_group 0;" ::: "memory")

#define PITCH 36
#define ROWPB (PITCH * 4)                 // 144 bytes per row
#define STGB  (256u * ROWPB)              // bytes per stage (36864), all modes
#define WSLAB 524288                      // bytes per weight slab in g_WT16

// ---------------------------------------------------------------------------
// bf16 mma.sync GEMM. ALL modes: 256 thr, 8 warps (4M x 2N), 2 CTAs/SM,
// CTA 128 M-rows x 128 B-rows, BK=64, cp.async 3-stage, ldmatrix x4,
// pitch 36 u32. Per k-step per warp: 6 LDSM -> 16 MMA.
//
// MODE 0: B rows = [Wr_x n0..n0+63 | Wz_x n0..n0+63], warp tile 32x32/weight,
//         N-tile 64, A = x16 ((b,t) map). Epi: r,z -> zr(bf16), z(bf16).
// MODE 1: K=1024: A = [zr | x], B = [Wh_h ; Wh_x], N-tile 128, warp 32x64.
//         Epi: hn = (1-z)h0 + z*tanh(acc+bh) -> bf16.
// MODE 2: K=512: A = hn, B = Wo, N-tile 128. Epi: sigmoid -> out.
// ---------------------------------------------------------------------------
template <int MODE>
__global__ __launch_bounds__(256, 2)
void kgemm(float* __restrict__ Cout, const float* __restrict__ bias,
           const float* __restrict__ h0, int Nt, int Tfull)
{
    constexpr int CHUNKS = (MODE == 1) ? 16 : 8;
    constexpr int W      = (MODE == 0) ? 2 : 1;
    constexpr int NT     = (MODE == 0) ? 4 : 8;
    constexpr int NTILE  = (MODE == 0) ? 64 : 128;
    constexpr int WNW    = (MODE == 0) ? 32 : 64;
    constexpr int NCHT   = 8;             // 16B chunks per thread (4 A + 4 B)

    extern __shared__ uint32_t sm[];
    const uint32_t sbase = smem_u32(sm);

    const int tid = threadIdx.x;
    const int wid = tid >> 5, lid = tid & 31;
    const int g = lid >> 2, t = lid & 3;
    const int warpM = wid & 3;
    const int warpN = wid >> 2;
    const int m0 = blockIdx.y * 128;
    const int n0 = blockIdx.x * NTILE;

    const char* xb  = (const char*)g_x16;
    const char* zrb = (const char*)g_zr16;
    const char* hnb = (const char*)g_hn16;
    const char* wtb = (const char*)g_WT16;

    // ---- per-slot byte offsets: slots 0..3 = A rows, 4..7 = B rows ----
    uint32_t offP[NCHT];
    uint32_t offX[4];
    uint32_t sofb[NCHT];
#pragma unroll
    for (int i = 0; i < NCHT; i++) {
        int c = tid + 256 * i;
        if (i < 4) {
            int row = c >> 3, q = c & 7;
            int gm = m0 + row;
            uint32_t xoff = (uint32_t)((long)(gm / Nt) * Tfull + (gm % Nt)) * 1024u + q * 16;
            if (MODE == 0) offP[i] = xoff;
            else           offP[i] = (uint32_t)gm * 1024u + q * 16;
            if (MODE == 1) offX[i] = xoff;
            sofb[i] = (uint32_t)row * ROWPB + q * 16;
        } else {
            int c2 = c - 1024;
            int brow = c2 >> 3, q = c2 & 7;
            if (MODE == 0) {
                int sel = brow >> 6, nr = brow & 63;     // 0=Wr_x, 1=Wz_x
                offP[i] = (uint32_t)sel * WSLAB + (uint32_t)(n0 + nr) * 1024u + q * 16;
            } else {
                offP[i] = (uint32_t)(n0 + brow) * 1024u + q * 16;   // slab added per chunk
            }
            sofb[i] = (uint32_t)(128 + brow) * ROWPB + q * 16;
        }
    }

    // ---- ldmatrix per-lane base addresses ----
    const uint32_t a_addr = sbase + (uint32_t)(warpM * 32 + (lid & 15)) * ROWPB
                          + ((lid & 16) ? 16 : 0);
    const int b_row = ((lid & 16) ? 8 : 0) + (lid & 7);
    const uint32_t b_addr = sbase + (uint32_t)(128 + b_row) * ROWPB + ((lid & 8) ? 16 : 0);

    uint32_t bgrp_off[4];
#pragma unroll
    for (int gb = 0; gb < 4; gb++) {
        int base = (MODE == 0) ? ((gb >> 1) * 64 + warpN * 32 + (gb & 1) * 16)  // (w, sub)
                               : (warpN * 64 + gb * 16);
        bgrp_off[gb] = (uint32_t)base * ROWPB;
    }

    float c[W][2][NT][4];
#pragma unroll
    for (int w = 0; w < W; w++)
#pragma unroll
        for (int mt = 0; mt < 2; mt++)
#pragma unroll
            for (int nt = 0; nt < NT; nt++)
#pragma unroll
                for (int q = 0; q < 4; q++) c[w][mt][nt][q] = 0.0f;

    // ---- cp.async issue for (slot i, chunk kt) ----
    auto issue = [&](int i, int kt, uint32_t stb) {
        const char* src;
        if (MODE == 0) {
            src = ((i < 4) ? xb : wtb) + offP[i] + kt * 128;
        } else if (MODE == 1) {
            if (i < 4) src = (kt < 8) ? (zrb + offP[i] + kt * 128)
                                      : (xb + offX[i < 4 ? i : 0] + (kt - 8) * 128);
            else       src = wtb + offP[i] + ((kt < 8) ? 3u : 2u) * WSLAB + (kt & 7) * 128;
        } else {
            src = ((i < 4) ? (hnb + offP[i]) : (wtb + offP[i] + 4u * WSLAB)) + kt * 128;
        }
        CP16(sbase + stb + sofb[i], src);
    };

    // ---- prologue: chunks 0,1 -> stages 0,1 ----
#pragma unroll
    for (int i = 0; i < NCHT; i++) issue(i, 0, 0);
    CP_COMMIT();
#pragma unroll
    for (int i = 0; i < NCHT; i++) issue(i, 1, STGB);
    CP_COMMIT();
    CP_WAIT1();
    __syncthreads();

    // ---- mainloop ----
    for (int kt = 0; kt < CHUNKS; kt++) {
        const uint32_t stb = (uint32_t)(kt % 3) * STGB;
        const bool pf = (kt < CHUNKS - 2);
        const uint32_t nstb = (uint32_t)((kt + 2) % 3) * STGB;

#pragma unroll
        for (int ks = 0; ks < 4; ks++) {
            if (pf) { issue(2 * ks, kt + 2, nstb); issue(2 * ks + 1, kt + 2, nstb); }
            uint32_t af4[2][4];
#pragma unroll
            for (int mt = 0; mt < 2; mt++)
                ldm4(af4[mt], a_addr + stb + (uint32_t)mt * (16 * ROWPB) + ks * 32);
            uint32_t bf4[4][4];
#pragma unroll
            for (int gb = 0; gb < 4; gb++)
                ldm4(bf4[gb], b_addr + stb + bgrp_off[gb] + ks * 32);

            if (MODE == 0) {
#pragma unroll
                for (int w = 0; w < 2; w++)
#pragma unroll
                    for (int mt = 0; mt < 2; mt++)
#pragma unroll
                        for (int nt = 0; nt < NT; nt++)
                            mma_bf16(c[w % W][mt][nt], af4[mt],
                                     &bf4[w * 2 + (nt >> 1)][(nt & 1) * 2]);
            } else {
#pragma unroll
                for (int mt = 0; mt < 2; mt++)
#pragma unroll
                    for (int nt = 0; nt < NT; nt++)
                        mma_bf16(c[0][mt][nt], af4[mt], &bf4[nt >> 1][(nt & 1) * 2]);
            }
        }

        if (pf) CP_COMMIT();
        if (kt < CHUNKS - 1) {
            if (pf) CP_WAIT1(); else CP_WAIT0();
            __syncthreads();
        }
    }

    // ---- epilogue ----
#pragma unroll
    for (int mt = 0; mt < 2; mt++) {
#pragma unroll
        for (int rh = 0; rh < 2; rh++) {
            const int m = m0 + warpM * 32 + mt * 16 + g + rh * 8;
            const int b = m / Nt;
#pragma unroll
            for (int nt = 0; nt < NT; nt++) {
                const int n = n0 + warpN * WNW + nt * 8 + t * 2;
                const long hidx = (long)m * 256 + (n >> 1);
                if (MODE == 0) {
                    float vr0 = c[0][mt][nt][rh * 2 + 0], vr1 = c[0][mt][nt][rh * 2 + 1];
                    float vz0 = c[1 % W][mt][nt][rh * 2 + 0], vz1 = c[1 % W][mt][nt][rh * 2 + 1];
                    float r0 = sigmoidf_(vr0 + g_hpr[b * 512 + n]);
                    float r1 = sigmoidf_(vr1 + g_hpr[b * 512 + n + 1]);
                    float z0 = sigmoidf_(vz0 + g_hpz[b * 512 + n]);
                    float z1 = sigmoidf_(vz1 + g_hpz[b * 512 + n + 1]);
                    g_zr16[hidx] = pk(z0 * r0, z1 * r1);
                    g_z16[hidx]  = pk(z0, z1);
                } else if (MODE == 1) {
                    float v0 = c[0][mt][nt][rh * 2 + 0], v1 = c[0][mt][nt][rh * 2 + 1];
                    float2 zv = upk(g_z16[hidx]);
                    float2 hv = *(const float2*)(h0 + b * 512 + n);
                    float2 bv = *(const float2*)(bias + n);
                    float o0 = (1.0f - zv.x) * hv.x + zv.x * tanhf(v0 + bv.x);
                    float o1 = (1.0f - zv.y) * hv.y + zv.y * tanhf(v1 + bv.y);
                    g_hn16[hidx] = pk(o0, o1);
                } else {
                    float v0 = c[0][mt][nt][rh * 2 + 0], v1 = c[0][mt][nt][rh * 2 + 1];
                    float2 bv = *(const float2*)(bias + n);
                    *(float2*)(Cout + (long)m * 512 + n) =
                        make_float2(sigmoidf_(v0 + bv.x), sigmoidf_(v1 + bv.y));
                }
            }
        }
    }
}

// ---------------------------------------------------------------------------
__global__ void cvt_x_kernel(const float* __restrict__ src, uint32_t* __restrict__ dst) {
    long i = (long)blockIdx.x * blockDim.x + threadIdx.x;
    float4 v = ((const float4*)src)[i];
    ((uint2*)dst)[i] = make_uint2(pk(v.x, v.y), pk(v.z, v.w));
}

__global__ void transpose_all_bf16(const float* __restrict__ Wr, const float* __restrict__ Wz,
                                   const float* __restrict__ Wh, const float* __restrict__ Wo,
                                   __nv_bfloat16* __restrict__ dst) {
    __shared__ float tbuf[32][33];
    const int sel = blockIdx.z;
    const float* src = (sel == 0) ? Wr : (sel == 1) ? Wz : (sel == 2) ? Wh
                     : (sel == 3) ? (Wh + (long)Ic * Hc) : Wo;
    __nv_bfloat16* d = dst + (long)sel * 512 * 512;
    int bx = blockIdx.x * 32, by = blockIdx.y * 32;
#pragma unroll
    for (int i = 0; i < 4; i++)
        tbuf[threadIdx.y + i * 8][threadIdx.x] = src[(long)(by + threadIdx.y + i * 8) * 512 + bx + threadIdx.x];
    __syncthreads();
#pragma unroll
    for (int i = 0; i < 4; i++)
        d[(long)(bx + threadIdx.y + i * 8) * 512 + by + threadIdx.x] =
            __float2bfloat16(tbuf[threadIdx.x][threadIdx.y + i * 8]);
}

__global__ void hpart_kernel(const float* __restrict__ h0, const float* __restrict__ Wr_h,
                             const float* __restrict__ br, const float* __restrict__ Wz_h,
                             const float* __restrict__ bz) {
    int b = blockIdx.x, n = threadIdx.x;
    float ar = br[n], az = bz[n];
    const float* h0b = h0 + b * Hc;
    for (int k = 0; k < Hc; k++) {
        float h = h0b[k];
        ar = fmaf(h, Wr_h[k * Hc + n], ar);
        az = fmaf(h, Wz_h[k * Hc + n], az);
    }
    g_hpr[b * Hc + n] = ar;
    g_hpz[b * Hc + n] = az;
}

__global__ void copy_h0_kernel(const float* __restrict__ h0, float* __restrict__ dst) {
    int i = blockIdx.x * blockDim.x + threadIdx.x;
    dst[i] = h0[i];
}

// ---------------------------------------------------------------------------
extern "C" void kernel_launch(void* const* d_in, const int* in_sizes, int n_in,
                              void* d_out, int out_size) {
    const float* x  = (const float*)d_in[0];
    const float* h0 = (const float*)d_in[1];
    const float* Wr = (const float*)d_in[2];
    const float* br = (const float*)d_in[3];
    const float* Wz = (const float*)d_in[4];
    const float* bz = (const float*)d_in[5];
    const float* Wh = (const float*)d_in[6];
    const float* bh = (const float*)d_in[7];
    const float* Wo = (const float*)d_in[8];
    const float* bo = (const float*)d_in[9];
    float* out = (float*)d_out;

    long os = out_size;
    int Tfull = in_sizes[0] / (Bc * Ic);
    int Nt;
    bool with_h0;
    if (os > (long)Bc * Hc && ((os - (long)Bc * Hc) % ((long)Bc * Oc)) == 0) {
        Nt = (int)((os - (long)Bc * Hc) / ((long)Bc * Oc));
        with_h0 = true;
    } else {
        Nt = (int)(os / ((long)Bc * Oc));
        with_h0 = false;
    }
    int M = Bc * Nt;

    const int smemB = 3 * STGB;   // 110592 for all modes
    cudaFuncSetAttribute(kgemm<0>, cudaFuncAttributeMaxDynamicSharedMemorySize, smemB);
    cudaFuncSetAttribute(kgemm<1>, cudaFuncAttributeMaxDynamicSharedMemorySize, smemB);
    cudaFuncSetAttribute(kgemm<2>, cudaFuncAttributeMaxDynamicSharedMemorySize, smemB);

    __nv_bfloat16* wt;
    cudaGetSymbolAddress((void**)&wt, g_WT16);
    uint32_t* x16;
    cudaGetSymbolAddress((void**)&x16, g_x16);

    transpose_all_bf16<<<dim3(16, 16, 5), dim3(32, 8)>>>(Wr, Wz, Wh, Wo, wt);

    long x4 = (long)in_sizes[0] / 4;
    cvt_x_kernel<<<(unsigned)(x4 / 256), 256>>>(x, x16);

    hpart_kernel<<<Bc, Hc>>>(h0, Wr + (long)Ic * Hc, br, Wz + (long)Ic * Hc, bz);

    // Stage 1: r,z gates (Wr_x, Wz_x fused), 2-CTA/SM shape
    kgemm<0><<<dim3(8, M / 128), 256, smemB>>>(nullptr, nullptr, nullptr, Nt, Tfull);
    // Stage 2: hn via K=1024 GEMM [zr|x] @ [Wh_h ; Wh_x]
    kgemm<1><<<dim3(4, M / 128), 256, smemB>>>(nullptr, bh, h0, Nt, Tfull);
    // Stage 3: out
    kgemm<2><<<dim3(4, M / 128), 256, smemB>>>(out, bo, nullptr, Nt, Tfull);

    if (with_h0)
        copy_h0_kernel<<<(Bc * Hc) / 256, 256>>>(h0, out + (long)M * Oc);
}

// round 14
// speedup vs baseline: 1.3110x; 1.0067x over previous
#include <cuda_runtime.h>
#include <cuda_bf16.h>
#include <cstdint>
#include <math.h>

#define Bc 64
#define Tc 512
#define Ic 512
#define Hc 512
#define Oc 512

// Scratch
__device__ uint32_t g_z16 [(long)Bc * Tc * Hc / 2];  // z (bf16x2)
__device__ uint32_t g_x16 [(long)Bc * Tc * Ic / 2];  // x as bf16x2
__device__ uint32_t g_zr16[(long)Bc * Tc * Hc / 2];  // zr (bf16x2)
__device__ uint32_t g_hn16[(long)Bc * Tc * Hc / 2];  // h_new (bf16x2)
__device__ float    g_hpr[Bc * Hc];
__device__ float    g_hpz[Bc * Hc];
__device__ __nv_bfloat16 g_WT16[5l * 512 * 512];     // W^T bf16 [sel][n][k]
// slabs: 0=Wr_x 1=Wz_x 2=Wh_x 3=Wh_h 4=Wo

__device__ __forceinline__ float sigmoidf_(float x) { return 1.0f / (1.0f + expf(-x)); }

__device__ __forceinline__ uint32_t pk(float lo, float hi) {
    __nv_bfloat162 h = __floats2bfloat162_rn(lo, hi);
    return *reinterpret_cast<uint32_t*>(&h);
}
__device__ __forceinline__ float2 upk(uint32_t u) {
    __nv_bfloat162 h = *reinterpret_cast<__nv_bfloat162*>(&u);
    return __bfloat1622float2(h);
}

__device__ __forceinline__ uint32_t smem_u32(const void* p) {
    uint32_t a;
    asm("{ .reg .u64 t; cvta.to.shared.u64 t, %1; cvt.u32.u64 %0, t; }" : "=r"(a) : "l"(p));
    return a;
}

__device__ __forceinline__ void mma_bf16(float* c, const uint32_t* a, const uint32_t* b) {
    asm volatile(
        "mma.sync.aligned.m16n8k16.row.col.f32.bf16.bf16.f32 "
        "{%0,%1,%2,%3}, {%4,%5,%6,%7}, {%8,%9}, {%0,%1,%2,%3};"
        : "+f"(c[0]), "+f"(c[1]), "+f"(c[2]), "+f"(c[3])
        : "r"(a[0]), "r"(a[1]), "r"(a[2]), "r"(a[3]), "r"(b[0]), "r"(b[1]));
}

__device__ __forceinline__ void ldm4(uint32_t* r, uint32_t addr) {
    asm volatile("ldmatrix.sync.aligned.m8n8.x4.shared.b16 {%0,%1,%2,%3}, [%4];"
                 : "=r"(r[0]), "=r"(r[1]), "=r"(r[2]), "=r"(r[3]) : "r"(addr));
}

#define CP16(saddr, gptr) asm volatile("cp.async.cg.shared.global [%0], [%1], 16;" :: "r"(saddr), "l"(gptr))
#define CP_COMMIT()       asm volatile("cp.async.commit_group;" ::: "memory")
#define CP_WAIT1()        asm volatile("cp.async.wait_group 1;" ::: "memory")
#define CP_WAIT0()        asm volatile("cp.async.wait_group 0;" ::: "memory")

#define PITCH 36
#define ROWPB (PITCH * 4)                 // 144 bytes per row
#define STGB  (256u * ROWPB)              // bytes per stage (36864), all modes
#define WSLAB 524288                      // bytes per weight slab in g_WT16

// ---------------------------------------------------------------------------
// bf16 mma.sync GEMM. ALL modes: 256 thr, 8 warps (4M x 2N), 2 CTAs/SM,
// CTA 128 M-rows x 128 B-rows, BK=64, cp.async 3-stage, ldmatrix x4,
// pitch 36 u32. Per k-step per warp: 6 LDSM -> 16 MMA. (R13 engine, frozen.)
// ---------------------------------------------------------------------------
template <int MODE>
__global__ __launch_bounds__(256, 2)
void kgemm(float* __restrict__ Cout, const float* __restrict__ bias,
           const float* __restrict__ h0, int Nt, int Tfull)
{
    constexpr int CHUNKS = (MODE == 1) ? 16 : 8;
    constexpr int W      = (MODE == 0) ? 2 : 1;
    constexpr int NT     = (MODE == 0) ? 4 : 8;
    constexpr int NTILE  = (MODE == 0) ? 64 : 128;
    constexpr int WNW    = (MODE == 0) ? 32 : 64;
    constexpr int NCHT   = 8;

    extern __shared__ uint32_t sm[];
    const uint32_t sbase = smem_u32(sm);

    const int tid = threadIdx.x;
    const int wid = tid >> 5, lid = tid & 31;
    const int g = lid >> 2, t = lid & 3;
    const int warpM = wid & 3;
    const int warpN = wid >> 2;
    const int m0 = blockIdx.y * 128;
    const int n0 = blockIdx.x * NTILE;

    const char* xb  = (const char*)g_x16;
    const char* zrb = (const char*)g_zr16;
    const char* hnb = (const char*)g_hn16;
    const char* wtb = (const char*)g_WT16;

    uint32_t offP[NCHT];
    uint32_t offX[4];
    uint32_t sofb[NCHT];
#pragma unroll
    for (int i = 0; i < NCHT; i++) {
        int c = tid + 256 * i;
        if (i < 4) {
            int row = c >> 3, q = c & 7;
            int gm = m0 + row;
            uint32_t xoff = (uint32_t)((long)(gm / Nt) * Tfull + (gm % Nt)) * 1024u + q * 16;
            if (MODE == 0) offP[i] = xoff;
            else           offP[i] = (uint32_t)gm * 1024u + q * 16;
            if (MODE == 1) offX[i] = xoff;
            sofb[i] = (uint32_t)row * ROWPB + q * 16;
        } else {
            int c2 = c - 1024;
            int brow = c2 >> 3, q = c2 & 7;
            if (MODE == 0) {
                int sel = brow >> 6, nr = brow & 63;
                offP[i] = (uint32_t)sel * WSLAB + (uint32_t)(n0 + nr) * 1024u + q * 16;
            } else {
                offP[i] = (uint32_t)(n0 + brow) * 1024u + q * 16;
            }
            sofb[i] = (uint32_t)(128 + brow) * ROWPB + q * 16;
        }
    }

    const uint32_t a_addr = sbase + (uint32_t)(warpM * 32 + (lid & 15)) * ROWPB
                          + ((lid & 16) ? 16 : 0);
    const int b_row = ((lid & 16) ? 8 : 0) + (lid & 7);
    const uint32_t b_addr = sbase + (uint32_t)(128 + b_row) * ROWPB + ((lid & 8) ? 16 : 0);

    uint32_t bgrp_off[4];
#pragma unroll
    for (int gb = 0; gb < 4; gb++) {
        int base = (MODE == 0) ? ((gb >> 1) * 64 + warpN * 32 + (gb & 1) * 16)
                               : (warpN * 64 + gb * 16);
        bgrp_off[gb] = (uint32_t)base * ROWPB;
    }

    float c[W][2][NT][4];
#pragma unroll
    for (int w = 0; w < W; w++)
#pragma unroll
        for (int mt = 0; mt < 2; mt++)
#pragma unroll
            for (int nt = 0; nt < NT; nt++)
#pragma unroll
                for (int q = 0; q < 4; q++) c[w][mt][nt][q] = 0.0f;

    auto issue = [&](int i, int kt, uint32_t stb) {
        const char* src;
        if (MODE == 0) {
            src = ((i < 4) ? xb : wtb) + offP[i] + kt * 128;
        } else if (MODE == 1) {
            if (i < 4) src = (kt < 8) ? (zrb + offP[i] + kt * 128)
                                      : (xb + offX[i < 4 ? i : 0] + (kt - 8) * 128);
            else       src = wtb + offP[i] + ((kt < 8) ? 3u : 2u) * WSLAB + (kt & 7) * 128;
        } else {
            src = ((i < 4) ? (hnb + offP[i]) : (wtb + offP[i] + 4u * WSLAB)) + kt * 128;
        }
        CP16(sbase + stb + sofb[i], src);
    };

#pragma unroll
    for (int i = 0; i < NCHT; i++) issue(i, 0, 0);
    CP_COMMIT();
#pragma unroll
    for (int i = 0; i < NCHT; i++) issue(i, 1, STGB);
    CP_COMMIT();
    CP_WAIT1();
    __syncthreads();

    for (int kt = 0; kt < CHUNKS; kt++) {
        const uint32_t stb = (uint32_t)(kt % 3) * STGB;
        const bool pf = (kt < CHUNKS - 2);
        const uint32_t nstb = (uint32_t)((kt + 2) % 3) * STGB;

#pragma unroll
        for (int ks = 0; ks < 4; ks++) {
            if (pf) { issue(2 * ks, kt + 2, nstb); issue(2 * ks + 1, kt + 2, nstb); }
            uint32_t af4[2][4];
#pragma unroll
            for (int mt = 0; mt < 2; mt++)
                ldm4(af4[mt], a_addr + stb + (uint32_t)mt * (16 * ROWPB) + ks * 32);
            uint32_t bf4[4][4];
#pragma unroll
            for (int gb = 0; gb < 4; gb++)
                ldm4(bf4[gb], b_addr + stb + bgrp_off[gb] + ks * 32);

            if (MODE == 0) {
#pragma unroll
                for (int w = 0; w < 2; w++)
#pragma unroll
                    for (int mt = 0; mt < 2; mt++)
#pragma unroll
                        for (int nt = 0; nt < NT; nt++)
                            mma_bf16(c[w % W][mt][nt], af4[mt],
                                     &bf4[w * 2 + (nt >> 1)][(nt & 1) * 2]);
            } else {
#pragma unroll
                for (int mt = 0; mt < 2; mt++)
#pragma unroll
                    for (int nt = 0; nt < NT; nt++)
                        mma_bf16(c[0][mt][nt], af4[mt], &bf4[nt >> 1][(nt & 1) * 2]);
            }
        }

        if (pf) CP_COMMIT();
        if (kt < CHUNKS - 1) {
            if (pf) CP_WAIT1(); else CP_WAIT0();
            __syncthreads();
        }
    }

#pragma unroll
    for (int mt = 0; mt < 2; mt++) {
#pragma unroll
        for (int rh = 0; rh < 2; rh++) {
            const int m = m0 + warpM * 32 + mt * 16 + g + rh * 8;
            const int b = m / Nt;
#pragma unroll
            for (int nt = 0; nt < NT; nt++) {
                const int n = n0 + warpN * WNW + nt * 8 + t * 2;
                const long hidx = (long)m * 256 + (n >> 1);
                if (MODE == 0) {
                    float vr0 = c[0][mt][nt][rh * 2 + 0], vr1 = c[0][mt][nt][rh * 2 + 1];
                    float vz0 = c[1 % W][mt][nt][rh * 2 + 0], vz1 = c[1 % W][mt][nt][rh * 2 + 1];
                    float r0 = sigmoidf_(vr0 + g_hpr[b * 512 + n]);
                    float r1 = sigmoidf_(vr1 + g_hpr[b * 512 + n + 1]);
                    float z0 = sigmoidf_(vz0 + g_hpz[b * 512 + n]);
                    float z1 = sigmoidf_(vz1 + g_hpz[b * 512 + n + 1]);
                    g_zr16[hidx] = pk(z0 * r0, z1 * r1);
                    g_z16[hidx]  = pk(z0, z1);
                } else if (MODE == 1) {
                    float v0 = c[0][mt][nt][rh * 2 + 0], v1 = c[0][mt][nt][rh * 2 + 1];
                    float2 zv = upk(g_z16[hidx]);
                    float2 hv = *(const float2*)(h0 + b * 512 + n);
                    float2 bv = *(const float2*)(bias + n);
                    float o0 = (1.0f - zv.x) * hv.x + zv.x * tanhf(v0 + bv.x);
                    float o1 = (1.0f - zv.y) * hv.y + zv.y * tanhf(v1 + bv.y);
                    g_hn16[hidx] = pk(o0, o1);
                } else {
                    float v0 = c[0][mt][nt][rh * 2 + 0], v1 = c[0][mt][nt][rh * 2 + 1];
                    float2 bv = *(const float2*)(bias + n);
                    *(float2*)(Cout + (long)m * 512 + n) =
                        make_float2(sigmoidf_(v0 + bv.x), sigmoidf_(v1 + bv.y));
                }
            }
        }
    }
}

// ---------------------------------------------------------------------------
// Fused prep kernel: blockIdx.z selects work.
//   z = 0..4 : transpose+cvt weight sel z into g_WT16 (grid 16x16, block 32x8)
//   z = 5    : hpart (g_hpr/g_hpz), first 128 of the 256 2D blocks
//   z = 6    : copy h0 -> out tail (if h0dst != null), first 128 blocks
// ---------------------------------------------------------------------------
__global__ void prep_kernel(const float* __restrict__ Wr, const float* __restrict__ Wz,
                            const float* __restrict__ Wh, const float* __restrict__ Wo,
                            __nv_bfloat16* __restrict__ wdst,
                            const float* __restrict__ h0,
                            const float* __restrict__ br, const float* __restrict__ bz,
                            float* __restrict__ h0dst) {
    const int z = blockIdx.z;
    if (z < 5) {
        __shared__ float tbuf[32][33];
        const float* src = (z == 0) ? Wr : (z == 1) ? Wz : (z == 2) ? Wh
                         : (z == 3) ? (Wh + (long)Ic * Hc) : Wo;
        __nv_bfloat16* d = wdst + (long)z * 512 * 512;
        int bx = blockIdx.x * 32, by = blockIdx.y * 32;
#pragma unroll
        for (int i = 0; i < 4; i++)
            tbuf[threadIdx.y + i * 8][threadIdx.x] =
                src[(long)(by + threadIdx.y + i * 8) * 512 + bx + threadIdx.x];
        __syncthreads();
#pragma unroll
        for (int i = 0; i < 4; i++)
            d[(long)(bx + threadIdx.y + i * 8) * 512 + by + threadIdx.x] =
                __float2bfloat16(tbuf[threadIdx.x][threadIdx.y + i * 8]);
        return;
    }
    const int tid = threadIdx.y * 32 + threadIdx.x;          // 0..255
    const int bid = blockIdx.y * 16 + blockIdx.x;            // 0..255
    if (bid >= 128) return;
    const int idx = bid * 256 + tid;                          // 0..32767
    if (z == 5) {
        const int b = idx >> 9, n = idx & 511;
        const float* Wr_h = Wr + (long)Ic * Hc;
        const float* Wz_h = Wz + (long)Ic * Hc;
        float ar = br[n], az = bz[n];
        const float* h0b = h0 + b * Hc;
        for (int k = 0; k < Hc; k++) {
            float h = h0b[k];
            ar = fmaf(h, Wr_h[k * Hc + n], ar);
            az = fmaf(h, Wz_h[k * Hc + n], az);
        }
        g_hpr[idx] = ar;
        g_hpz[idx] = az;
    } else {
        if (h0dst) h0dst[idx] = h0[idx];
    }
}

__global__ void cvt_x_kernel(const float* __restrict__ src, uint32_t* __restrict__ dst) {
    long i = (long)blockIdx.x * blockDim.x + threadIdx.x;
    float4 v = ((const float4*)src)[i];
    ((uint2*)dst)[i] = make_uint2(pk(v.x, v.y), pk(v.z, v.w));
}

// ---------------------------------------------------------------------------
extern "C" void kernel_launch(void* const* d_in, const int* in_sizes, int n_in,
                              void* d_out, int out_size) {
    const float* x  = (const float*)d_in[0];
    const float* h0 = (const float*)d_in[1];
    const float* Wr = (const float*)d_in[2];
    const float* br = (const float*)d_in[3];
    const float* Wz = (const float*)d_in[4];
    const float* bz = (const float*)d_in[5];
    const float* Wh = (const float*)d_in[6];
    const float* bh = (const float*)d_in[7];
    const float* Wo = (const float*)d_in[8];
    const float* bo = (const float*)d_in[9];
    float* out = (float*)d_out;

    long os = out_size;
    int Tfull = in_sizes[0] / (Bc * Ic);
    int Nt;
    bool with_h0;
    if (os > (long)Bc * Hc && ((os - (long)Bc * Hc) % ((long)Bc * Oc)) == 0) {
        Nt = (int)((os - (long)Bc * Hc) / ((long)Bc * Oc));
        with_h0 = true;
    } else {
        Nt = (int)(os / ((long)Bc * Oc));
        with_h0 = false;
    }
    int M = Bc * Nt;

    const int smemB = 3 * STGB;   // 110592 for all modes
    cudaFuncSetAttribute(kgemm<0>, cudaFuncAttributeMaxDynamicSharedMemorySize, smemB);
    cudaFuncSetAttribute(kgemm<1>, cudaFuncAttributeMaxDynamicSharedMemorySize, smemB);
    cudaFuncSetAttribute(kgemm<2>, cudaFuncAttributeMaxDynamicSharedMemorySize, smemB);

    __nv_bfloat16* wt;
    cudaGetSymbolAddress((void**)&wt, g_WT16);
    uint32_t* x16;
    cudaGetSymbolAddress((void**)&x16, g_x16);

    // Fused prep: 5 weight transposes + hpart + h0 tail copy in one launch
    float* h0dst = with_h0 ? (out + (long)M * Oc) : nullptr;
    prep_kernel<<<dim3(16, 16, 7), dim3(32, 8)>>>(Wr, Wz, Wh, Wo, wt, h0, br, bz, h0dst);

    long x4 = (long)in_sizes[0] / 4;
    cvt_x_kernel<<<(unsigned)(x4 / 256), 256>>>(x, x16);

    // Stage 1: r,z gates (Wr_x, Wz_x fused)
    kgemm<0><<<dim3(8, M / 128), 256, smemB>>>(nullptr, nullptr, nullptr, Nt, Tfull);
    // Stage 2: hn via K=1024 GEMM [zr|x] @ [Wh_h ; Wh_x]
    kgemm<1><<<dim3(4, M / 128), 256, smemB>>>(nullptr, bh, h0, Nt, Tfull);
    // Stage 3: out
    kgemm<2><<<dim3(4, M / 128), 256, smemB>>>(out, bo, nullptr, Nt, Tfull);
}

// round 15
// speedup vs baseline: 1.3417x; 1.0234x over previous
#include <cuda_runtime.h>
#include <cuda_bf16.h>
#include <cstdint>
#include <math.h>

#define Bc 64
#define Tc 512
#define Ic 512
#define Hc 512
#define Oc 512

// Scratch
__device__ uint32_t g_z16 [(long)Bc * Tc * Hc / 2];  // z (bf16x2)
__device__ uint32_t g_x16 [(long)Bc * Tc * Ic / 2];  // x as bf16x2
__device__ uint32_t g_zr16[(long)Bc * Tc * Hc / 2];  // zr (bf16x2)
__device__ uint32_t g_hn16[(long)Bc * Tc * Hc / 2];  // h_new (bf16x2)
__device__ float    g_hpr[Bc * Hc];
__device__ float    g_hpz[Bc * Hc];
__device__ __nv_bfloat16 g_WT16[5l * 512 * 512];     // W^T bf16 [sel][n][k]
// slabs: 0=Wr_x 1=Wz_x 2=Wh_x 3=Wh_h 4=Wo

__device__ __forceinline__ float sigmoidf_(float x) { return 1.0f / (1.0f + expf(-x)); }

__device__ __forceinline__ uint32_t pk(float lo, float hi) {
    __nv_bfloat162 h = __floats2bfloat162_rn(lo, hi);
    return *reinterpret_cast<uint32_t*>(&h);
}
__device__ __forceinline__ float2 upk(uint32_t u) {
    __nv_bfloat162 h = *reinterpret_cast<__nv_bfloat162*>(&u);
    return __bfloat1622float2(h);
}

__device__ __forceinline__ uint32_t smem_u32(const void* p) {
    uint32_t a;
    asm("{ .reg .u64 t; cvta.to.shared.u64 t, %1; cvt.u32.u64 %0, t; }" : "=r"(a) : "l"(p));
    return a;
}

__device__ __forceinline__ void gdc_wait()   { asm volatile("griddepcontrol.wait;" ::: "memory"); }
__device__ __forceinline__ void gdc_launch() { asm volatile("griddepcontrol.launch_dependents;" ::: "memory"); }

__device__ __forceinline__ void mma_bf16(float* c, const uint32_t* a, const uint32_t* b) {
    asm volatile(
        "mma.sync.aligned.m16n8k16.row.col.f32.bf16.bf16.f32 "
        "{%0,%1,%2,%3}, {%4,%5,%6,%7}, {%8,%9}, {%0,%1,%2,%3};"
        : "+f"(c[0]), "+f"(c[1]), "+f"(c[2]), "+f"(c[3])
        : "r"(a[0]), "r"(a[1]), "r"(a[2]), "r"(a[3]), "r"(b[0]), "r"(b[1]));
}

__device__ __forceinline__ void ldm4(uint32_t* r, uint32_t addr) {
    asm volatile("ldmatrix.sync.aligned.m8n8.x4.shared.b16 {%0,%1,%2,%3}, [%4];"
                 : "=r"(r[0]), "=r"(r[1]), "=r"(r[2]), "=r"(r[3]) : "r"(addr));
}

#define CP16(saddr, gptr) asm volatile("cp.async.cg.shared.global [%0], [%1], 16;" :: "r"(saddr), "l"(gptr))
#define CP_COMMIT()       asm volatile("cp.async.commit_group;" ::: "memory")
#define CP_WAIT1()        asm volatile("cp.async.wait_group 1;" ::: "memory")
#define CP_WAIT0()        asm volatile("cp.async.wait_group 0;" ::: "memory")

#define PITCH 36
#define ROWPB (PITCH * 4)                 // 144 bytes per row
#define STGB  (256u * ROWPB)              // bytes per stage (36864), all modes
#define WSLAB 524288                      // bytes per weight slab in g_WT16

// ---------------------------------------------------------------------------
// bf16 mma.sync GEMM (R13 engine). ALL modes: 256 thr, 8 warps (4M x 2N),
// 2 CTAs/SM, CTA 128M x 128 B-rows, BK=64, cp.async 3-stage, ldmatrix x4.
// PDL: B-weight prefetch pre-wait (weights are >=2 PDL hops upstream),
// griddepcontrol.wait before A issues, launch_dependents after mainloop.
// ---------------------------------------------------------------------------
template <int MODE>
__global__ __launch_bounds__(256, 2)
void kgemm(float* __restrict__ Cout, const float* __restrict__ bias,
           const float* __restrict__ h0, int Nt, int Tfull)
{
    constexpr int CHUNKS = (MODE == 1) ? 16 : 8;
    constexpr int W      = (MODE == 0) ? 2 : 1;
    constexpr int NT     = (MODE == 0) ? 4 : 8;
    constexpr int NTILE  = (MODE == 0) ? 64 : 128;
    constexpr int WNW    = (MODE == 0) ? 32 : 64;
    constexpr int NCHT   = 8;

    extern __shared__ uint32_t sm[];
    const uint32_t sbase = smem_u32(sm);

    const int tid = threadIdx.x;
    const int wid = tid >> 5, lid = tid & 31;
    const int g = lid >> 2, t = lid & 3;
    const int warpM = wid & 3;
    const int warpN = wid >> 2;
    const int m0 = blockIdx.y * 128;
    const int n0 = blockIdx.x * NTILE;

    const char* xb  = (const char*)g_x16;
    const char* zrb = (const char*)g_zr16;
    const char* hnb = (const char*)g_hn16;
    const char* wtb = (const char*)g_WT16;

    uint32_t offP[NCHT];
    uint32_t offX[4];
    uint32_t sofb[NCHT];
#pragma unroll
    for (int i = 0; i < NCHT; i++) {
        int c = tid + 256 * i;
        if (i < 4) {
            int row = c >> 3, q = c & 7;
            int gm = m0 + row;
            uint32_t xoff = (uint32_t)((long)(gm / Nt) * Tfull + (gm % Nt)) * 1024u + q * 16;
            if (MODE == 0) offP[i] = xoff;
            else           offP[i] = (uint32_t)gm * 1024u + q * 16;
            if (MODE == 1) offX[i] = xoff;
            sofb[i] = (uint32_t)row * ROWPB + q * 16;
        } else {
            int c2 = c - 1024;
            int brow = c2 >> 3, q = c2 & 7;
            if (MODE == 0) {
                int sel = brow >> 6, nr = brow & 63;
                offP[i] = (uint32_t)sel * WSLAB + (uint32_t)(n0 + nr) * 1024u + q * 16;
            } else {
                offP[i] = (uint32_t)(n0 + brow) * 1024u + q * 16;
            }
            sofb[i] = (uint32_t)(128 + brow) * ROWPB + q * 16;
        }
    }

    const uint32_t a_addr = sbase + (uint32_t)(warpM * 32 + (lid & 15)) * ROWPB
                          + ((lid & 16) ? 16 : 0);
    const int b_row = ((lid & 16) ? 8 : 0) + (lid & 7);
    const uint32_t b_addr = sbase + (uint32_t)(128 + b_row) * ROWPB + ((lid & 8) ? 16 : 0);

    uint32_t bgrp_off[4];
#pragma unroll
    for (int gb = 0; gb < 4; gb++) {
        int base = (MODE == 0) ? ((gb >> 1) * 64 + warpN * 32 + (gb & 1) * 16)
                               : (warpN * 64 + gb * 16);
        bgrp_off[gb] = (uint32_t)base * ROWPB;
    }

    float c[W][2][NT][4];
#pragma unroll
    for (int w = 0; w < W; w++)
#pragma unroll
        for (int mt = 0; mt < 2; mt++)
#pragma unroll
            for (int nt = 0; nt < NT; nt++)
#pragma unroll
                for (int q = 0; q < 4; q++) c[w][mt][nt][q] = 0.0f;

    auto issue = [&](int i, int kt, uint32_t stb) {
        const char* src;
        if (MODE == 0) {
            src = ((i < 4) ? xb : wtb) + offP[i] + kt * 128;
        } else if (MODE == 1) {
            if (i < 4) src = (kt < 8) ? (zrb + offP[i] + kt * 128)
                                      : (xb + offX[i < 4 ? i : 0] + (kt - 8) * 128);
            else       src = wtb + offP[i] + ((kt < 8) ? 3u : 2u) * WSLAB + (kt & 7) * 128;
        } else {
            src = ((i < 4) ? (hnb + offP[i]) : (wtb + offP[i] + 4u * WSLAB)) + kt * 128;
        }
        CP16(sbase + stb + sofb[i], src);
    };

    // ---- prologue with PDL overlap ----
    if (MODE == 0) {
        // Both A (x16) and B (weights) come from the immediate predecessor: wait first.
        gdc_wait();
#pragma unroll
        for (int i = 0; i < NCHT; i++) issue(i, 0, 0);
        CP_COMMIT();
#pragma unroll
        for (int i = 0; i < NCHT; i++) issue(i, 1, STGB);
        CP_COMMIT();
    } else {
        // Weights are >=2 PDL hops upstream (complete): prefetch B pre-wait.
#pragma unroll
        for (int i = 4; i < NCHT; i++) issue(i, 0, 0);
#pragma unroll
        for (int i = 4; i < NCHT; i++) issue(i, 1, STGB);
        gdc_wait();
#pragma unroll
        for (int i = 0; i < 4; i++) issue(i, 0, 0);
        CP_COMMIT();          // group0 = {B ch0, B ch1, A ch0}
#pragma unroll
        for (int i = 0; i < 4; i++) issue(i, 1, STGB);
        CP_COMMIT();          // group1 = {A ch1}
    }
    CP_WAIT1();
    __syncthreads();

    // ---- mainloop ----
    for (int kt = 0; kt < CHUNKS; kt++) {
        const uint32_t stb = (uint32_t)(kt % 3) * STGB;
        const bool pf = (kt < CHUNKS - 2);
        const uint32_t nstb = (uint32_t)((kt + 2) % 3) * STGB;

#pragma unroll
        for (int ks = 0; ks < 4; ks++) {
            if (pf) { issue(2 * ks, kt + 2, nstb); issue(2 * ks + 1, kt + 2, nstb); }
            uint32_t af4[2][4];
#pragma unroll
            for (int mt = 0; mt < 2; mt++)
                ldm4(af4[mt], a_addr + stb + (uint32_t)mt * (16 * ROWPB) + ks * 32);
            uint32_t bf4[4][4];
#pragma unroll
            for (int gb = 0; gb < 4; gb++)
                ldm4(bf4[gb], b_addr + stb + bgrp_off[gb] + ks * 32);

            if (MODE == 0) {
#pragma unroll
                for (int w = 0; w < 2; w++)
#pragma unroll
                    for (int mt = 0; mt < 2; mt++)
#pragma unroll
                        for (int nt = 0; nt < NT; nt++)
                            mma_bf16(c[w % W][mt][nt], af4[mt],
                                     &bf4[w * 2 + (nt >> 1)][(nt & 1) * 2]);
            } else {
#pragma unroll
                for (int mt = 0; mt < 2; mt++)
#pragma unroll
                    for (int nt = 0; nt < NT; nt++)
                        mma_bf16(c[0][mt][nt], af4[mt], &bf4[nt >> 1][(nt & 1) * 2]);
            }
        }

        if (pf) CP_COMMIT();
        if (kt < CHUNKS - 1) {
            if (pf) CP_WAIT1(); else CP_WAIT0();
            __syncthreads();
        }
    }

    // Allow dependent kernel to start overlapping our epilogue/drain.
    gdc_launch();

    // ---- epilogue ----
#pragma unroll
    for (int mt = 0; mt < 2; mt++) {
#pragma unroll
        for (int rh = 0; rh < 2; rh++) {
            const int m = m0 + warpM * 32 + mt * 16 + g + rh * 8;
            const int b = m / Nt;
#pragma unroll
            for (int nt = 0; nt < NT; nt++) {
                const int n = n0 + warpN * WNW + nt * 8 + t * 2;
                const long hidx = (long)m * 256 + (n >> 1);
                if (MODE == 0) {
                    float vr0 = c[0][mt][nt][rh * 2 + 0], vr1 = c[0][mt][nt][rh * 2 + 1];
                    float vz0 = c[1 % W][mt][nt][rh * 2 + 0], vz1 = c[1 % W][mt][nt][rh * 2 + 1];
                    float r0 = sigmoidf_(vr0 + g_hpr[b * 512 + n]);
                    float r1 = sigmoidf_(vr1 + g_hpr[b * 512 + n + 1]);
                    float z0 = sigmoidf_(vz0 + g_hpz[b * 512 + n]);
                    float z1 = sigmoidf_(vz1 + g_hpz[b * 512 + n + 1]);
                    g_zr16[hidx] = pk(z0 * r0, z1 * r1);
                    g_z16[hidx]  = pk(z0, z1);
                } else if (MODE == 1) {
                    float v0 = c[0][mt][nt][rh * 2 + 0], v1 = c[0][mt][nt][rh * 2 + 1];
                    float2 zv = upk(g_z16[hidx]);
                    float2 hv = *(const float2*)(h0 + b * 512 + n);
                    float2 bv = *(const float2*)(bias + n);
                    float o0 = (1.0f - zv.x) * hv.x + zv.x * tanhf(v0 + bv.x);
                    float o1 = (1.0f - zv.y) * hv.y + zv.y * tanhf(v1 + bv.y);
                    g_hn16[hidx] = pk(o0, o1);
                } else {
                    float v0 = c[0][mt][nt][rh * 2 + 0], v1 = c[0][mt][nt][rh * 2 + 1];
                    float2 bv = *(const float2*)(bias + n);
                    *(float2*)(Cout + (long)m * 512 + n) =
                        make_float2(sigmoidf_(v0 + bv.x), sigmoidf_(v1 + bv.y));
                }
            }
        }
    }
}

// ---------------------------------------------------------------------------
// Fused prep kernel: blockIdx.z selects work.
//   z = 0..4  : transpose+cvt weight sel z into g_WT16
//   z = 5     : hpart (g_hpr/g_hpz), first 128 of 256 blocks
//   z = 6     : copy h0 -> out tail (if h0dst != null), first 128 blocks
//   z >= 7    : x fp32 -> bf16x2 conversion (grid-stride over float4s)
// ---------------------------------------------------------------------------
__global__ void prep_kernel(const float* __restrict__ Wr, const float* __restrict__ Wz,
                            const float* __restrict__ Wh, const float* __restrict__ Wo,
                            __nv_bfloat16* __restrict__ wdst,
                            const float* __restrict__ h0,
                            const float* __restrict__ br, const float* __restrict__ bz,
                            float* __restrict__ h0dst,
                            const float* __restrict__ x, uint32_t* __restrict__ x16,
                            long x4) {
    const int z = blockIdx.z;
    if (z < 5) {
        __shared__ float tbuf[32][33];
        const float* src = (z == 0) ? Wr : (z == 1) ? Wz : (z == 2) ? Wh
                         : (z == 3) ? (Wh + (long)Ic * Hc) : Wo;
        __nv_bfloat16* d = wdst + (long)z * 512 * 512;
        int bx = blockIdx.x * 32, by = blockIdx.y * 32;
#pragma unroll
        for (int i = 0; i < 4; i++)
            tbuf[threadIdx.y + i * 8][threadIdx.x] =
                src[(long)(by + threadIdx.y + i * 8) * 512 + bx + threadIdx.x];
        __syncthreads();
#pragma unroll
        for (int i = 0; i < 4; i++)
            d[(long)(bx + threadIdx.y + i * 8) * 512 + by + threadIdx.x] =
                __float2bfloat16(tbuf[threadIdx.x][threadIdx.y + i * 8]);
        gdc_launch();
        return;
    }
    const int tid = threadIdx.y * 32 + threadIdx.x;          // 0..255
    const int bid = blockIdx.y * 16 + blockIdx.x;            // 0..255
    if (z == 5) {
        if (bid < 128) {
            const int idx = bid * 256 + tid;
            const int b = idx >> 9, n = idx & 511;
            const float* Wr_h = Wr + (long)Ic * Hc;
            const float* Wz_h = Wz + (long)Ic * Hc;
            float ar = br[n], az = bz[n];
            const float* h0b = h0 + b * Hc;
            for (int k = 0; k < Hc; k++) {
                float h = h0b[k];
                ar = fmaf(h, Wr_h[k * Hc + n], ar);
                az = fmaf(h, Wz_h[k * Hc + n], az);
            }
            g_hpr[idx] = ar;
            g_hpz[idx] = az;
        }
    } else if (z == 6) {
        if (bid < 128 && h0dst) {
            const int idx = bid * 256 + tid;
            h0dst[idx] = h0[idx];
        }
    } else {
        // x conversion: plane p handles 256 blocks * 256 thr * 4 float4s
        const long base = ((long)(z - 7) * 256 + bid) * 1024;
#pragma unroll
        for (int it = 0; it < 4; it++) {
            long i = base + it * 256 + tid;
            if (i < x4) {
                float4 v = ((const float4*)x)[i];
                ((uint2*)x16)[i] = make_uint2(pk(v.x, v.y), pk(v.z, v.w));
            }
        }
    }
    gdc_launch();
}

// ---------------------------------------------------------------------------
extern "C" void kernel_launch(void* const* d_in, const int* in_sizes, int n_in,
                              void* d_out, int out_size) {
    const float* x  = (const float*)d_in[0];
    const float* h0 = (const float*)d_in[1];
    const float* Wr = (const float*)d_in[2];
    const float* br = (const float*)d_in[3];
    const float* Wz = (const float*)d_in[4];
    const float* bz = (const float*)d_in[5];
    const float* Wh = (const float*)d_in[6];
    const float* bh = (const float*)d_in[7];
    const float* Wo = (const float*)d_in[8];
    const float* bo = (const float*)d_in[9];
    float* out = (float*)d_out;

    long os = out_size;
    int Tfull = in_sizes[0] / (Bc * Ic);
    int Nt;
    bool with_h0;
    if (os > (long)Bc * Hc && ((os - (long)Bc * Hc) % ((long)Bc * Oc)) == 0) {
        Nt = (int)((os - (long)Bc * Hc) / ((long)Bc * Oc));
        with_h0 = true;
    } else {
        Nt = (int)(os / ((long)Bc * Oc));
        with_h0 = false;
    }
    int M = Bc * Nt;

    const int smemB = 3 * STGB;   // 110592 for all modes
    cudaFuncSetAttribute(kgemm<0>, cudaFuncAttributeMaxDynamicSharedMemorySize, smemB);
    cudaFuncSetAttribute(kgemm<1>, cudaFuncAttributeMaxDynamicSharedMemorySize, smemB);
    cudaFuncSetAttribute(kgemm<2>, cudaFuncAttributeMaxDynamicSharedMemorySize, smemB);

    __nv_bfloat16* wt;
    cudaGetSymbolAddress((void**)&wt, g_WT16);
    uint32_t* x16;
    cudaGetSymbolAddress((void**)&x16, g_x16);

    // Fused prep: transposes + hpart + h0 tail + x conversion, one launch
    long x4 = (long)in_sizes[0] / 4;
    int cvtPlanes = (int)((x4 + 262143) / 262144);
    float* h0dst = with_h0 ? (out + (long)M * Oc) : nullptr;
    prep_kernel<<<dim3(16, 16, 7 + cvtPlanes), dim3(32, 8)>>>(
        Wr, Wz, Wh, Wo, wt, h0, br, bz, h0dst, x, x16, x4);

    // GEMMs with programmatic dependent launch
    cudaLaunchAttribute attrs[1];
    attrs[0].id = cudaLaunchAttributeProgrammaticStreamSerialization;
    attrs[0].val.programmaticStreamSerializationAllowed = 1;

    cudaLaunchConfig_t cfg = {};
    cfg.blockDim = {256, 1, 1};
    cfg.dynamicSmemBytes = smemB;
    cfg.stream = 0;
    cfg.attrs = attrs;
    cfg.numAttrs = 1;

    float* nullf = nullptr;

    cfg.gridDim = {8, (unsigned)(M / 128), 1};
    cudaLaunchKernelEx(&cfg, kgemm<0>, nullf, (const float*)nullptr, (const float*)nullptr, Nt, Tfull);

    cfg.gridDim = {4, (unsigned)(M / 128), 1};
    cudaLaunchKernelEx(&cfg, kgemm<1>, nullf, bh, h0, Nt, Tfull);

    cfg.gridDim = {4, (unsigned)(M / 128), 1};
    cudaLaunchKernelEx(&cfg, kgemm<2>, out, bo, (const float*)nullptr, Nt, Tfull);
}